// round 8
// baseline (speedup 1.0000x reference)
#include <cuda_runtime.h>
#include <math.h>

#define B_  4
#define S_  2048
#define DM  1024
#define NH  16
#define NKV 4
#define HD  64
#define KVD 256
#define CH  64
#define NC  32
#define TOK (B_*S_)

// ---------------- device scratch (static; no allocation) ----------------
__device__ float g_xq[(size_t)TOK*DM];
__device__ float g_xk[(size_t)TOK*KVD];
__device__ float g_xv[(size_t)TOK*KVD];
__device__ float g_M[(size_t)2*B_*KVD*DM];
__device__ float g_kmem[(size_t)TOK*KVD];
__device__ float g_vmem[(size_t)TOK*KVD];
__device__ float g_q[(size_t)B_*NH*S_*HD];
__device__ float g_k[(size_t)B_*NKV*S_*HD];
__device__ float g_v[(size_t)B_*NKV*S_*HD];
__device__ float g_ao[(size_t)TOK*DM];

// ln(500000)
#define LOG_ROPE_BASE 13.122363377404331

// ---------------- naive tiled GEMM: C[M,N] = A[M,K] @ B[K,N] ----------------
__global__ void gemm_nn(const float* __restrict__ A, const float* __restrict__ B,
                        float* __restrict__ C, int M, int N, int K) {
    __shared__ float As[16][16];
    __shared__ float Bs[16][17];
    int row = blockIdx.y*16 + threadIdx.y;
    int col = blockIdx.x*16 + threadIdx.x;
    float acc = 0.f;
    for (int k0 = 0; k0 < K; k0 += 16) {
        As[threadIdx.y][threadIdx.x] = A[(size_t)row*K + k0 + threadIdx.x];
        Bs[threadIdx.y][threadIdx.x] = B[(size_t)(k0 + threadIdx.y)*N + col];
        __syncthreads();
        #pragma unroll
        for (int k = 0; k < 16; k++) acc += As[threadIdx.y][k] * Bs[k][threadIdx.x];
        __syncthreads();
    }
    C[(size_t)row*N + col] = acc;
}

// ---------------- M init: M[m][b] = M0[m] ----------------
__global__ void k_minit(const float* __restrict__ M0) {
    size_t idx = (size_t)blockIdx.x*256 + threadIdx.x;
    if (idx >= (size_t)2*B_*KVD*DM) return;
    size_t m = idx / ((size_t)B_*KVD*DM);
    size_t r = idx % ((size_t)KVD*DM);
    g_M[idx] = M0[m*((size_t)KVD*DM) + r];
}

// ---------------- one chunk of the delta-memory scan (literal reference) ----
// grid (B_, 2), 1024 threads. Phases:
//  0: per-token L2 norms + per-token hyperparam sigmoids
//  1: retrieval out[t][o] = c_t . M_o (pre-update M) -> g_kmem/g_vmem, vt = sum_t out
//  2: kmean[d] = mean_t c[t][d]/norm_t
//  3: err[o] = vt[o]/64 - M_o . kmean ; gate = sigmoid(kmean.gw + gb); eta/alpha means
//  4: M = aco*M + bco*err⊗kmean ; Frobenius clamp
__global__ __launch_bounds__(1024) void mem_chunk(
    const float* __restrict__ x,
    const float* __restrict__ ew, const float* __restrict__ eb,
    const float* __restrict__ aw, const float* __restrict__ ab,
    const float* __restrict__ gw, const float* __restrict__ gb,
    int ci)
{
    int b = blockIdx.x, m = blockIdx.y;
    int tid = threadIdx.x, w = tid >> 5, lane = tid & 31;
    float* M = g_M + ((size_t)(m*B_ + b))*KVD*DM;
    const float* c = x + ((size_t)b*S_ + (size_t)ci*CH)*DM;
    float* outbuf = (m == 0 ? g_kmem : g_vmem) + ((size_t)b*S_ + (size_t)ci*CH)*KVD;

    __shared__ float inorm[CH];
    __shared__ float hypE[CH];
    __shared__ float hypA[CH];
    __shared__ float km[DM];
    __shared__ float vt[KVD];
    __shared__ float err[KVD];
    __shared__ float red[32];
    __shared__ float sh[4];

    // Phase 0
    if (tid < CH) {
        const float* row = c + (size_t)tid*DM;
        float sq = 0.f, de = 0.f, da = 0.f;
        for (int d = 0; d < DM; d++) {
            float v = row[d];
            sq += v*v;
            de += v*ew[m*DM + d];
            da += v*aw[m*DM + d];
        }
        inorm[tid] = 1.f / fmaxf(sqrtf(sq), 1e-5f);
        hypE[tid] = 1.f/(1.f + expf(-(de + eb[m])));
        hypA[tid] = 1.f/(1.f + expf(-(da + ab[m])));
    }
    if (tid < KVD) vt[tid] = 0.f;
    __syncthreads();

    // Phase 1: retrieval with PRE-update M
    for (int idx = tid; idx < CH*KVD; idx += 1024) {
        int o = idx & (KVD-1), t = idx >> 8;
        const float* crow = c + (size_t)t*DM;
        const float* Mrow = M + (size_t)o*DM;
        float s = 0.f;
        for (int d = 0; d < DM; d++) s += crow[d]*Mrow[d];
        outbuf[(size_t)t*KVD + o] = s;
        atomicAdd(&vt[o], s);
    }
    __syncthreads();

    // Phase 2: kmean
    {
        int d = tid;   // blockDim == DM
        float s = 0.f;
        for (int t = 0; t < CH; t++) s += c[(size_t)t*DM + d] * inorm[t];
        km[d] = s * (1.f/64.f);
    }
    __syncthreads();

    // Phase 3
    if (tid < KVD) {
        const float* Mrow = M + (size_t)tid*DM;
        float s = 0.f;
        for (int d = 0; d < DM; d++) s += Mrow[d]*km[d];
        err[tid] = vt[tid]*(1.f/64.f) - s;
    }
    {
        float gp = km[tid] * gw[m*DM + tid];
        #pragma unroll
        for (int off = 16; off; off >>= 1) gp += __shfl_xor_sync(0xffffffffu, gp, off);
        if (lane == 0) red[w] = gp;
    }
    __syncthreads();
    if (tid == 0) {
        float gdot = 0.f;
        for (int ww = 0; ww < 32; ww++) gdot += red[ww];
        sh[0] = 1.f/(1.f + expf(-(gdot + gb[m])));
        float se = 0.f, sa = 0.f;
        for (int t = 0; t < CH; t++) { se += hypE[t]; sa += hypA[t]; }
        sh[1] = 0.2f * se * (1.f/64.f);                  // eta
        sh[2] = 0.5f + 0.5f * sa * (1.f/64.f);           // alpha
    }
    __syncthreads();
    float gt = sh[0], eta = sh[1], al = sh[2];
    float aco = gt*al + 1.f - gt;
    float bco = gt*eta;

    // Phase 4: update + Frobenius clamp
    float ss = 0.f;
    for (int l = tid; l < KVD*DM; l += 1024) {
        int o = l >> 10, d = l & (DM-1);
        float nv = aco*M[l] + bco*err[o]*km[d];
        M[l] = nv;
        ss += nv*nv;
    }
    #pragma unroll
    for (int off = 16; off; off >>= 1) ss += __shfl_xor_sync(0xffffffffu, ss, off);
    if (lane == 0) red[w] = ss;
    __syncthreads();
    if (tid == 0) {
        float tot = 0.f;
        for (int ww = 0; ww < 32; ww++) tot += red[ww];
        sh[3] = fminf(30.f/(sqrtf(tot) + 1e-6f), 1.f);
    }
    __syncthreads();
    float sc = sh[3];
    for (int l = tid; l < KVD*DM; l += 1024) M[l] *= sc;
}

// ---------------- q build with RoPE (double-precision trig) ----------------
__global__ void q_build() {
    size_t idx = (size_t)blockIdx.x*256 + threadIdx.x;
    if (idx >= (size_t)TOK*DM) return;
    int col = (int)(idx & (DM-1));
    size_t t = idx >> 10;
    int b = (int)(t >> 11), pos = (int)(t & 2047);
    int h = col >> 6, d = col & 63;
    float qc = g_xq[idx];
    int pd = (d < 32) ? d + 32 : d - 32;
    float qp = g_xq[(t << 10) + h*64 + pd];
    float rot = (d < 32) ? -qp : qp;
    double f = exp(-(double)(d & 31) * (LOG_ROPE_BASE/32.0));
    double ds, dc;
    sincos((double)pos * f, &ds, &dc);
    g_q[(((size_t)b*NH + h)*S_ + pos)*HD + d] = qc*(float)dc + rot*(float)ds;
}

// ---------------- k build: (Wk x + k_mem) then RoPE ----------------
__global__ void k_build() {
    size_t idx = (size_t)blockIdx.x*256 + threadIdx.x;
    if (idx >= (size_t)TOK*KVD) return;
    int o = (int)(idx & (KVD-1));
    size_t t = idx >> 8;
    int b = (int)(t >> 11), pos = (int)(t & 2047);
    int kv = o >> 6, d = o & 63;
    float kc = g_xk[idx] + g_kmem[idx];
    int pd = (d < 32) ? d + 32 : d - 32;
    size_t pidx = (t << 8) + kv*64 + pd;
    float kp = g_xk[pidx] + g_kmem[pidx];
    float rot = (d < 32) ? -kp : kp;
    double f = exp(-(double)(d & 31) * (LOG_ROPE_BASE/32.0));
    double ds, dc;
    sincos((double)pos * f, &ds, &dc);
    g_k[(((size_t)b*NKV + kv)*S_ + pos)*HD + d] = kc*(float)dc + rot*(float)ds;
}

// ---------------- v build: Wv x + v_mem ----------------
__global__ void v_build() {
    size_t idx = (size_t)blockIdx.x*256 + threadIdx.x;
    if (idx >= (size_t)TOK*KVD) return;
    int o = (int)(idx & (KVD-1));
    size_t t = idx >> 8;
    int b = (int)(t >> 11), pos = (int)(t & 2047);
    int kv = o >> 6, d = o & 63;
    g_v[(((size_t)b*NKV + kv)*S_ + pos)*HD + d] = g_xv[idx] + g_vmem[idx];
}

// ---------------- causal attention: 1 thread = 1 query row (plain expf) ----
__global__ __launch_bounds__(64) void k_attn() {
    __shared__ float Ks[64*64];
    __shared__ float Vs[64*64];
    int qt = blockIdx.x, h = blockIdx.y, b = blockIdx.z;
    int tid = threadIdx.x;
    int qg = qt*64 + tid;
    const float* qptr = g_q + (((size_t)b*NH + h)*S_ + qg)*HD;
    float qv[64], o[64];
    #pragma unroll
    for (int c = 0; c < 64; c++) { qv[c] = qptr[c] * 0.125f; o[c] = 0.f; }
    float mrun = -1e30f, lrun = 0.f;
    int kvh = h >> 2;
    const float* Kbase = g_k + ((size_t)b*NKV + kvh)*S_*HD;
    const float* Vbase = g_v + ((size_t)b*NKV + kvh)*S_*HD;
    for (int kt = 0; kt <= qt; kt++) {
        #pragma unroll
        for (int q = 0; q < 16; q++) {
            *reinterpret_cast<float4*>(&Ks[tid*64 + q*4]) =
                *reinterpret_cast<const float4*>(&Kbase[(size_t)(kt*64 + tid)*HD + q*4]);
            *reinterpret_cast<float4*>(&Vs[tid*64 + q*4]) =
                *reinterpret_cast<const float4*>(&Vbase[(size_t)(kt*64 + tid)*HD + q*4]);
        }
        __syncthreads();
        int kmax = (kt == qt) ? tid : 63;
        for (int kk = 0; kk <= kmax; kk++) {
            const float* kr = &Ks[kk*64];
            float s = 0.f;
            #pragma unroll
            for (int d = 0; d < 64; d++) s += qv[d]*kr[d];
            float mnew = fmaxf(mrun, s);
            float corr = expf(mrun - mnew);
            float p = expf(s - mnew);
            lrun = lrun*corr + p;
            const float* vr = &Vs[kk*64];
            #pragma unroll
            for (int d = 0; d < 64; d++) o[d] = o[d]*corr + p*vr[d];
            mrun = mnew;
        }
        __syncthreads();
    }
    float inv = 1.f / lrun;
    float* op = g_ao + ((size_t)(b*S_ + qg))*DM + h*HD;
    #pragma unroll
    for (int c = 0; c < 64; c++) op[c] = o[c]*inv;
}

// ---------------- host launch with size-based input routing ----------------
extern "C" void kernel_launch(void* const* d_in, const int* in_sizes, int n_in,
                              void* d_out, int out_size) {
    (void)out_size;
    const float *x = 0, *Wq = 0, *Wk = 0, *Wv = 0, *Wo = 0, *M0 = 0;
    const float *ew = 0, *eb = 0, *aw = 0, *ab = 0, *gw = 0, *gb = 0;
    int n1M = 0, n256K = 0, n2K = 0, nB = 0;
    for (int i = 0; i < n_in; i++) {
        const float* p = (const float*)d_in[i];
        switch (in_sizes[i]) {
            case 8388608: x = p; break;                       // B*S*DM
            case  524288: M0 = p; break;                      // 2*KVD*DM
            case 1048576: if (n1M++ == 0) Wq = p; else Wo = p; break;
            case  262144: if (n256K++ == 0) Wk = p; else Wv = p; break;
            case    2048: { if (n2K == 0) ew = p; else if (n2K == 1) aw = p; else gw = p; n2K++; } break;
            case       2: { if (nB == 0) eb = p; else if (nB == 1) ab = p; else gb = p; nB++; } break;
            default: break;
        }
    }
    float* out = (float*)d_out;

    float *pXq = 0, *pAo = 0;
    cudaGetSymbolAddress((void**)&pXq, g_xq);
    cudaGetSymbolAddress((void**)&pAo, g_ao);
    float *pXk = 0, *pXv = 0;
    cudaGetSymbolAddress((void**)&pXk, g_xk);
    cudaGetSymbolAddress((void**)&pXv, g_xv);

    // projections
    gemm_nn<<<dim3(DM/16,  TOK/16), dim3(16,16)>>>(x, Wq, pXq, TOK, DM,  DM);
    gemm_nn<<<dim3(KVD/16, TOK/16), dim3(16,16)>>>(x, Wk, pXk, TOK, KVD, DM);
    gemm_nn<<<dim3(KVD/16, TOK/16), dim3(16,16)>>>(x, Wv, pXv, TOK, KVD, DM);

    // memory scan
    k_minit<<<(int)(((size_t)2*B_*KVD*DM + 255)/256), 256>>>(M0);
    for (int ci = 0; ci < NC; ci++)
        mem_chunk<<<dim3(B_, 2), 1024>>>(x, ew, eb, aw, ab, gw, gb, ci);

    // q/k/v assembly + rope
    q_build<<<(int)(((size_t)TOK*DM  + 255)/256), 256>>>();
    k_build<<<(int)(((size_t)TOK*KVD + 255)/256), 256>>>();
    v_build<<<(int)(((size_t)TOK*KVD + 255)/256), 256>>>();

    // attention + output projection
    k_attn<<<dim3(S_/64, NH, B_), 64>>>();
    gemm_nn<<<dim3(DM/16, TOK/16), dim3(16,16)>>>(pAo, Wo, out, TOK, DM, DM);
}

// round 9
// speedup vs baseline: 24.2571x; 24.2571x over previous
#include <cuda_runtime.h>
#include <math.h>

#define B_  4
#define S_  2048
#define DM  1024
#define NH  16
#define NKV 4
#define HD  64
#define KVD 256
#define CH  64
#define NC  32
#define TOK (B_*S_)

// ---------------- device scratch (static; no allocation) ----------------
__device__ float g_xq[(size_t)TOK*DM];
__device__ float g_xk[(size_t)TOK*KVD];
__device__ float g_xv[(size_t)TOK*KVD];
__device__ float g_M[(size_t)2*B_*KVD*DM];
__device__ float g_kmem[(size_t)TOK*KVD];
__device__ float g_vmem[(size_t)TOK*KVD];
__device__ float g_q[(size_t)B_*NH*S_*HD];
__device__ float g_k[(size_t)B_*NKV*S_*HD];
__device__ float g_v[(size_t)B_*NKV*S_*HD];
__device__ float g_ao[(size_t)TOK*DM];
__device__ float g_cos[S_*32];
__device__ float g_sin[S_*32];

// ln(500000)
#define LOG_ROPE_BASE 13.122363377404331

// ---------------- RoPE trig table (double precision, computed once-per-call) -
__global__ void k_trig() {
    int idx = blockIdx.x*256 + threadIdx.x;
    if (idx >= S_*32) return;
    int pos = idx >> 5, fi = idx & 31;
    double f = exp(-(double)fi * (LOG_ROPE_BASE/32.0));
    double ds, dc;
    sincos((double)pos * f, &ds, &dc);
    g_cos[idx] = (float)dc;
    g_sin[idx] = (float)ds;
}

// ---------------- fast SGEMM: C[M,N] = A[M,K] @ B[K,N], 128x128x16 ----------
__global__ __launch_bounds__(256) void k_sgemm(const float* __restrict__ A,
                                               const float* __restrict__ B,
                                               float* __restrict__ C,
                                               int M, int N, int K) {
    __shared__ float As[16][128];
    __shared__ float Bs[16][132];
    int tid = threadIdx.x;
    int bm = blockIdx.y * 128, bn = blockIdx.x * 128;
    int tx = tid & 15, ty = tid >> 4;
    float acc[8][8];
    #pragma unroll
    for (int i = 0; i < 8; i++)
        #pragma unroll
        for (int j = 0; j < 8; j++) acc[i][j] = 0.f;
    for (int k0 = 0; k0 < K; k0 += 16) {
        #pragma unroll
        for (int it = 0; it < 2; it++) {
            int idx = tid + it*256;
            int row = idx >> 2, q = idx & 3;
            float4 v = *reinterpret_cast<const float4*>(&A[(size_t)(bm+row)*K + k0 + q*4]);
            As[q*4+0][row] = v.x; As[q*4+1][row] = v.y;
            As[q*4+2][row] = v.z; As[q*4+3][row] = v.w;
        }
        #pragma unroll
        for (int it = 0; it < 2; it++) {
            int idx = tid + it*256;
            int row = idx >> 5, q = idx & 31;
            float4 v = *reinterpret_cast<const float4*>(&B[(size_t)(k0+row)*N + bn + q*4]);
            Bs[row][q*4+0] = v.x; Bs[row][q*4+1] = v.y;
            Bs[row][q*4+2] = v.z; Bs[row][q*4+3] = v.w;
        }
        __syncthreads();
        #pragma unroll
        for (int kk = 0; kk < 16; kk++) {
            float a[8], b[8];
            #pragma unroll
            for (int i = 0; i < 8; i++) a[i] = As[kk][ty*8+i];
            #pragma unroll
            for (int j = 0; j < 8; j++) b[j] = Bs[kk][tx + 16*j];   // conflict-free
            #pragma unroll
            for (int i = 0; i < 8; i++)
                #pragma unroll
                for (int j = 0; j < 8; j++) acc[i][j] += a[i]*b[j];
        }
        __syncthreads();
    }
    #pragma unroll
    for (int i = 0; i < 8; i++)
        #pragma unroll
        for (int j = 0; j < 8; j++)
            C[(size_t)(bm+ty*8+i)*N + bn + tx + 16*j] = acc[i][j];
}

// ---------------- M init ----------------
__global__ void k_minit(const float* __restrict__ M0) {
    size_t idx = (size_t)blockIdx.x*256 + threadIdx.x;
    if (idx >= (size_t)2*B_*KVD*DM) return;
    size_t m = idx / ((size_t)B_*KVD*DM);
    size_t r = idx % ((size_t)KVD*DM);
    g_M[idx] = M0[m*((size_t)KVD*DM) + r];
}

// ---------------- one chunk of the delta-memory scan (optimized) ----------
// grid (B_, 2), 512 threads. Same phase semantics as validated R7 version.
__global__ __launch_bounds__(512) void mem_chunk(
    const float* __restrict__ x,
    const float* __restrict__ ew, const float* __restrict__ eb,
    const float* __restrict__ aw, const float* __restrict__ ab,
    const float* __restrict__ gw, const float* __restrict__ gb,
    int ci)
{
    int b = blockIdx.x, m = blockIdx.y;
    int tid = threadIdx.x, w = tid >> 5, lane = tid & 31;
    float* M = g_M + ((size_t)(m*B_ + b))*KVD*DM;
    const float* c = x + ((size_t)b*S_ + (size_t)ci*CH)*DM;
    float* outbuf = (m == 0 ? g_kmem : g_vmem) + ((size_t)b*S_ + (size_t)ci*CH)*KVD;

    __shared__ float inorm[CH];
    __shared__ float km[DM];
    __shared__ float vt[KVD];
    __shared__ float err[KVD];
    __shared__ float red[16];
    __shared__ float sh[4];      // [0]=sumSigE, [1]=sumSigA, [2]=gate, [3]=scale
    __shared__ float As[16][68];
    __shared__ float Bs[16][260];

    if (tid < 2) sh[tid] = 0.f;
    __syncthreads();

    // ---- Phase 0: per-token norms + hyperparam sigmoid sums (warp/token) ----
    for (int t = w; t < CH; t += 16) {
        const float* row = c + (size_t)t*DM;
        float sq = 0.f, de = 0.f, da = 0.f;
        for (int d = lane; d < DM; d += 32) {
            float v = row[d];
            sq += v*v;
            de += v*ew[m*DM + d];
            da += v*aw[m*DM + d];
        }
        #pragma unroll
        for (int off = 16; off; off >>= 1) {
            sq += __shfl_xor_sync(0xffffffffu, sq, off);
            de += __shfl_xor_sync(0xffffffffu, de, off);
            da += __shfl_xor_sync(0xffffffffu, da, off);
        }
        if (lane == 0) {
            inorm[t] = 1.f / fmaxf(sqrtf(sq), 1e-5f);
            atomicAdd(&sh[0], 1.f/(1.f + expf(-(de + eb[m]))));
            atomicAdd(&sh[1], 1.f/(1.f + expf(-(da + ab[m]))));
        }
    }
    __syncthreads();

    // ---- kmean (coalesced across threads) ----
    for (int d = tid; d < DM; d += 512) {
        float s = 0.f;
        for (int t = 0; t < CH; t++) s += c[(size_t)t*DM + d] * inorm[t];
        km[d] = s * (1.f/64.f);
    }
    __syncthreads();

    // ---- Phase 1: tiled retrieval out[64t][256o] = c @ M^T (pre-update M) ----
    float acc[8][8];
    #pragma unroll
    for (int i = 0; i < 8; i++)
        #pragma unroll
        for (int j = 0; j < 8; j++) acc[i][j] = 0.f;
    int ty = (tid >> 5) & 7, tx = tid & 31;
    for (int k0 = 0; k0 < DM; k0 += 16) {
        if (tid < 256) {                       // As: 64t x 16k
            int t = tid >> 2, q = tid & 3;
            float4 v = *reinterpret_cast<const float4*>(&c[(size_t)t*DM + k0 + q*4]);
            As[q*4+0][t] = v.x; As[q*4+1][t] = v.y;
            As[q*4+2][t] = v.z; As[q*4+3][t] = v.w;
        }
        #pragma unroll
        for (int it = 0; it < 2; it++) {       // Bs: 256o x 16k
            int idx = tid + it*512;
            int o = idx >> 2, q = idx & 3;
            float4 v = *reinterpret_cast<const float4*>(&M[(size_t)o*DM + k0 + q*4]);
            Bs[q*4+0][o] = v.x; Bs[q*4+1][o] = v.y;
            Bs[q*4+2][o] = v.z; Bs[q*4+3][o] = v.w;
        }
        __syncthreads();
        if (tid < 256) {
            #pragma unroll
            for (int k = 0; k < 16; k++) {
                float a[8], bb[8];
                #pragma unroll
                for (int i = 0; i < 8; i++) a[i] = As[k][ty*8+i];
                #pragma unroll
                for (int j = 0; j < 8; j++) bb[j] = Bs[k][tx + 32*j];
                #pragma unroll
                for (int i = 0; i < 8; i++)
                    #pragma unroll
                    for (int j = 0; j < 8; j++) acc[i][j] += a[i]*bb[j];
            }
        }
        __syncthreads();
    }
    if (tid < 256) {
        #pragma unroll
        for (int i = 0; i < 8; i++)
            #pragma unroll
            for (int j = 0; j < 8; j++)
                outbuf[(size_t)(ty*8+i)*KVD + tx + 32*j] = acc[i][j];
    }
    __syncthreads();
    if (tid < KVD) {
        float s = 0.f;
        for (int t = 0; t < CH; t++) s += outbuf[(size_t)t*KVD + tid];
        vt[tid] = s * (1.f/64.f);
    }
    __syncthreads();

    // ---- Phase 3: err = vt - M.kmean (warp-parallel), gate ----
    for (int oo = 0; oo < 16; oo++) {
        int o = w*16 + oo;
        const float* Mrow = M + (size_t)o*DM;
        float s = 0.f;
        for (int d = lane; d < DM; d += 32) s += Mrow[d]*km[d];
        #pragma unroll
        for (int off = 16; off; off >>= 1) s += __shfl_xor_sync(0xffffffffu, s, off);
        if (lane == 0) err[o] = vt[o] - s;
    }
    {
        float gp = km[tid]*gw[m*DM + tid] + km[tid+512]*gw[m*DM + tid + 512];
        #pragma unroll
        for (int off = 16; off; off >>= 1) gp += __shfl_xor_sync(0xffffffffu, gp, off);
        if (lane == 0) red[w] = gp;
    }
    __syncthreads();
    if (tid == 0) {
        float gdot = 0.f;
        for (int ww = 0; ww < 16; ww++) gdot += red[ww];
        sh[2] = 1.f/(1.f + expf(-(gdot + gb[m])));
    }
    __syncthreads();
    float gt = sh[2];
    float eta = 0.2f * sh[0] * (1.f/64.f);
    float al  = 0.5f + 0.5f * sh[1] * (1.f/64.f);
    float aco = gt*al + 1.f - gt;
    float bco = gt*eta;

    // ---- Phase 4: update (float4) + Frobenius clamp ----
    float ss = 0.f;
    float4* M4 = reinterpret_cast<float4*>(M);
    for (int i4 = tid; i4 < KVD*DM/4; i4 += 512) {
        int o = i4 >> 8;
        int db = (i4 & 255) * 4;
        float eo = bco * err[o];
        float4 mv = M4[i4];
        mv.x = aco*mv.x + eo*km[db+0];
        mv.y = aco*mv.y + eo*km[db+1];
        mv.z = aco*mv.z + eo*km[db+2];
        mv.w = aco*mv.w + eo*km[db+3];
        M4[i4] = mv;
        ss += mv.x*mv.x + mv.y*mv.y + mv.z*mv.z + mv.w*mv.w;
    }
    #pragma unroll
    for (int off = 16; off; off >>= 1) ss += __shfl_xor_sync(0xffffffffu, ss, off);
    if (lane == 0) red[w] = ss;
    __syncthreads();
    if (tid == 0) {
        float tot = 0.f;
        for (int ww = 0; ww < 16; ww++) tot += red[ww];
        sh[3] = fminf(30.f/(sqrtf(tot) + 1e-6f), 1.f);
    }
    __syncthreads();
    float sc = sh[3];
    if (sc != 1.f)
        for (int i4 = tid; i4 < KVD*DM/4; i4 += 512) {
            float4 mv = M4[i4];
            mv.x *= sc; mv.y *= sc; mv.z *= sc; mv.w *= sc;
            M4[i4] = mv;
        }
}

// ---------------- q build with RoPE (table) ----------------
__global__ void q_build() {
    size_t idx = (size_t)blockIdx.x*256 + threadIdx.x;
    if (idx >= (size_t)TOK*DM) return;
    int col = (int)(idx & (DM-1));
    size_t t = idx >> 10;
    int b = (int)(t >> 11), pos = (int)(t & 2047);
    int h = col >> 6, d = col & 63;
    float qc = g_xq[idx];
    int pd = (d < 32) ? d + 32 : d - 32;
    float qp = g_xq[(t << 10) + h*64 + pd];
    float rot = (d < 32) ? -qp : qp;
    float cs = g_cos[pos*32 + (d & 31)], sn = g_sin[pos*32 + (d & 31)];
    g_q[(((size_t)b*NH + h)*S_ + pos)*HD + d] = qc*cs + rot*sn;
}

// ---------------- k build: (Wk x + k_mem) then RoPE ----------------
__global__ void k_build() {
    size_t idx = (size_t)blockIdx.x*256 + threadIdx.x;
    if (idx >= (size_t)TOK*KVD) return;
    int o = (int)(idx & (KVD-1));
    size_t t = idx >> 8;
    int b = (int)(t >> 11), pos = (int)(t & 2047);
    int kv = o >> 6, d = o & 63;
    float kc = g_xk[idx] + g_kmem[idx];
    int pd = (d < 32) ? d + 32 : d - 32;
    size_t pidx = (t << 8) + kv*64 + pd;
    float kp = g_xk[pidx] + g_kmem[pidx];
    float rot = (d < 32) ? -kp : kp;
    float cs = g_cos[pos*32 + (d & 31)], sn = g_sin[pos*32 + (d & 31)];
    g_k[(((size_t)b*NKV + kv)*S_ + pos)*HD + d] = kc*cs + rot*sn;
}

// ---------------- v build ----------------
__global__ void v_build() {
    size_t idx = (size_t)blockIdx.x*256 + threadIdx.x;
    if (idx >= (size_t)TOK*KVD) return;
    int o = (int)(idx & (KVD-1));
    size_t t = idx >> 8;
    int b = (int)(t >> 11), pos = (int)(t & 2047);
    int kv = o >> 6, d = o & 63;
    g_v[(((size_t)b*NKV + kv)*S_ + pos)*HD + d] = g_xv[idx] + g_vmem[idx];
}

// ---------------- causal flash attention: 4 lanes/query, 16 cols each -------
__global__ __launch_bounds__(256) void k_attn() {
    extern __shared__ float sm[];
    float* Ks = sm;            // 64*64
    float* Vs = Ks + 4096;     // 64*64
    float* Ss = Vs + 4096;     // 64*65 (padded)
    int qt = blockIdx.x, h = blockIdx.y, b = blockIdx.z;
    int tid = threadIdx.x;
    int qr = tid >> 2, seg = tid & 3;
    int qg = qt*64 + qr;
    const float* qptr = g_q + (((size_t)b*NH + h)*S_ + qg)*HD + seg*16;
    float qv[16], o[16];
    #pragma unroll
    for (int c = 0; c < 16; c++) { qv[c] = qptr[c] * 0.125f; o[c] = 0.f; }
    float mrun = -1e30f, lrun = 0.f;
    int kvh = h >> 2;
    const float* Kbase = g_k + ((size_t)b*NKV + kvh)*S_*HD;
    const float* Vbase = g_v + ((size_t)b*NKV + kvh)*S_*HD;
    for (int kt = 0; kt <= qt; kt++) {
        #pragma unroll
        for (int it = 0; it < 4; it++) {
            int lin = tid + it*256;
            int r = lin >> 4, q = lin & 15;
            *reinterpret_cast<float4*>(&Ks[r*64 + q*4]) =
                *reinterpret_cast<const float4*>(&Kbase[(size_t)(kt*64 + r)*HD + q*4]);
            *reinterpret_cast<float4*>(&Vs[r*64 + q*4]) =
                *reinterpret_cast<const float4*>(&Vbase[(size_t)(kt*64 + r)*HD + q*4]);
        }
        __syncthreads();
        for (int kk = 0; kk < 64; kk++) {
            const float* kr = &Ks[kk*64 + seg*16];
            float s = 0.f;
            #pragma unroll
            for (int c = 0; c < 16; c += 4) {
                float4 kq = *reinterpret_cast<const float4*>(&kr[c]);
                s += qv[c]*kq.x + qv[c+1]*kq.y + qv[c+2]*kq.z + qv[c+3]*kq.w;
            }
            s += __shfl_xor_sync(0xffffffffu, s, 1);
            s += __shfl_xor_sync(0xffffffffu, s, 2);
            if (kt == qt && kk > qr) s = -1e30f;
            if ((kk & 3) == seg) Ss[qr*65 + kk] = s;
        }
        __syncthreads();
        // quarter-local max, shfl-combined (race-free by construction)
        float tq = -1e30f;
        #pragma unroll
        for (int kk2 = 0; kk2 < 16; kk2++) tq = fmaxf(tq, Ss[qr*65 + seg*16 + kk2]);
        tq = fmaxf(tq, __shfl_xor_sync(0xffffffffu, tq, 1));
        tq = fmaxf(tq, __shfl_xor_sync(0xffffffffu, tq, 2));
        float tmax = fmaxf(mrun, tq);
        float corr = __expf(mrun - tmax);
        mrun = tmax;
        lrun *= corr;
        #pragma unroll
        for (int c = 0; c < 16; c++) o[c] *= corr;
        float lpart = 0.f;
        #pragma unroll
        for (int kk2 = 0; kk2 < 16; kk2++) {
            int kk = seg*16 + kk2;
            float p = __expf(Ss[qr*65 + kk] - tmax);
            Ss[qr*65 + kk] = p;
            lpart += p;
        }
        lpart += __shfl_xor_sync(0xffffffffu, lpart, 1);
        lpart += __shfl_xor_sync(0xffffffffu, lpart, 2);
        lrun += lpart;
        __syncwarp();
        for (int kk = 0; kk < 64; kk++) {
            float p = Ss[qr*65 + kk];
            const float* vr = &Vs[kk*64 + seg*16];
            #pragma unroll
            for (int c = 0; c < 16; c += 4) {
                float4 vq = *reinterpret_cast<const float4*>(&vr[c]);
                o[c]   += p*vq.x; o[c+1] += p*vq.y;
                o[c+2] += p*vq.z; o[c+3] += p*vq.w;
            }
        }
        __syncthreads();
    }
    float inv = 1.f / lrun;
    float* op = g_ao + ((size_t)(b*S_ + qg))*DM + h*HD + seg*16;
    #pragma unroll
    for (int c = 0; c < 16; c++) op[c] = o[c]*inv;
}

// ---------------- host launch with size-based input routing ----------------
extern "C" void kernel_launch(void* const* d_in, const int* in_sizes, int n_in,
                              void* d_out, int out_size) {
    (void)out_size;
    const float *x = 0, *Wq = 0, *Wk = 0, *Wv = 0, *Wo = 0, *M0 = 0;
    const float *ew = 0, *eb = 0, *aw = 0, *ab = 0, *gw = 0, *gb = 0;
    int n1M = 0, n256K = 0, n2K = 0, nB = 0;
    for (int i = 0; i < n_in; i++) {
        const float* p = (const float*)d_in[i];
        switch (in_sizes[i]) {
            case 8388608: x = p; break;
            case  524288: M0 = p; break;
            case 1048576: if (n1M++ == 0) Wq = p; else Wo = p; break;
            case  262144: if (n256K++ == 0) Wk = p; else Wv = p; break;
            case    2048: { if (n2K == 0) ew = p; else if (n2K == 1) aw = p; else gw = p; n2K++; } break;
            case       2: { if (nB == 0) eb = p; else if (nB == 1) ab = p; else gb = p; nB++; } break;
            default: break;
        }
    }
    float* out = (float*)d_out;

    float *pXq = 0, *pXk = 0, *pXv = 0, *pAo = 0;
    cudaGetSymbolAddress((void**)&pXq, g_xq);
    cudaGetSymbolAddress((void**)&pXk, g_xk);
    cudaGetSymbolAddress((void**)&pXv, g_xv);
    cudaGetSymbolAddress((void**)&pAo, g_ao);

    cudaFuncSetAttribute(k_attn, cudaFuncAttributeMaxDynamicSharedMemorySize, 49408);

    k_trig<<<(S_*32 + 255)/256, 256>>>();

    // projections (fast SGEMM)
    k_sgemm<<<dim3(DM/128,  TOK/128), 256>>>(x, Wq, pXq, TOK, DM,  DM);
    k_sgemm<<<dim3(KVD/128, TOK/128), 256>>>(x, Wk, pXk, TOK, KVD, DM);
    k_sgemm<<<dim3(KVD/128, TOK/128), 256>>>(x, Wv, pXv, TOK, KVD, DM);

    // memory scan
    k_minit<<<(int)(((size_t)2*B_*KVD*DM + 255)/256), 256>>>(M0);
    for (int ci = 0; ci < NC; ci++)
        mem_chunk<<<dim3(B_, 2), 512>>>(x, ew, eb, aw, ab, gw, gb, ci);

    // q/k/v assembly + rope
    q_build<<<(int)(((size_t)TOK*DM  + 255)/256), 256>>>();
    k_build<<<(int)(((size_t)TOK*KVD + 255)/256), 256>>>();
    v_build<<<(int)(((size_t)TOK*KVD + 255)/256), 256>>>();

    // attention + output projection
    k_attn<<<dim3(S_/64, NH, B_), 256, 49408>>>();
    k_sgemm<<<dim3(DM/128, TOK/128), 256>>>(pAo, Wo, out, TOK, DM, DM);
}

// round 10
// speedup vs baseline: 32.1634x; 1.3259x over previous
#include <cuda_runtime.h>
#include <math.h>

#define B_  4
#define S_  2048
#define DM  1024
#define NH  16
#define NKV 4
#define HD  64
#define KVD 256
#define CH  64
#define NC  32
#define TOK (B_*S_)

// ---------------- device scratch (static; no allocation) ----------------
__device__ float g_xq[(size_t)TOK*DM];
__device__ float g_xk[(size_t)TOK*KVD];
__device__ float g_xv[(size_t)TOK*KVD];
__device__ float g_M[(size_t)2*B_*KVD*DM];
__device__ float g_kmem[(size_t)TOK*KVD];
__device__ float g_vmem[(size_t)TOK*KVD];
__device__ float g_q[(size_t)B_*NH*S_*HD];
__device__ float g_k[(size_t)B_*NKV*S_*HD];
__device__ float g_v[(size_t)B_*NKV*S_*HD];
__device__ float g_ao[(size_t)TOK*DM];
__device__ float g_cos[S_*32];
__device__ float g_sin[S_*32];

// ln(500000)
#define LOG_ROPE_BASE 13.122363377404331

// ---------------- RoPE trig table ----------------
__global__ void k_trig() {
    int idx = blockIdx.x*256 + threadIdx.x;
    if (idx >= S_*32) return;
    int pos = idx >> 5, fi = idx & 31;
    double f = exp(-(double)fi * (LOG_ROPE_BASE/32.0));
    double ds, dc;
    sincos((double)pos * f, &ds, &dc);
    g_cos[idx] = (float)dc;
    g_sin[idx] = (float)ds;
}

// ---------------- fast SGEMM: C[M,N] = A[M,K] @ B[K,N], 128x128x16 ----------
__global__ __launch_bounds__(256) void k_sgemm(const float* __restrict__ A,
                                               const float* __restrict__ B,
                                               float* __restrict__ C,
                                               int M, int N, int K) {
    __shared__ float As[16][128];
    __shared__ float Bs[16][132];
    int tid = threadIdx.x;
    int bm = blockIdx.y * 128, bn = blockIdx.x * 128;
    int tx = tid & 15, ty = tid >> 4;
    float acc[8][8];
    #pragma unroll
    for (int i = 0; i < 8; i++)
        #pragma unroll
        for (int j = 0; j < 8; j++) acc[i][j] = 0.f;
    for (int k0 = 0; k0 < K; k0 += 16) {
        #pragma unroll
        for (int it = 0; it < 2; it++) {
            int idx = tid + it*256;
            int row = idx >> 2, q = idx & 3;
            float4 v = *reinterpret_cast<const float4*>(&A[(size_t)(bm+row)*K + k0 + q*4]);
            As[q*4+0][row] = v.x; As[q*4+1][row] = v.y;
            As[q*4+2][row] = v.z; As[q*4+3][row] = v.w;
        }
        #pragma unroll
        for (int it = 0; it < 2; it++) {
            int idx = tid + it*256;
            int row = idx >> 5, q = idx & 31;
            float4 v = *reinterpret_cast<const float4*>(&B[(size_t)(k0+row)*N + bn + q*4]);
            Bs[row][q*4+0] = v.x; Bs[row][q*4+1] = v.y;
            Bs[row][q*4+2] = v.z; Bs[row][q*4+3] = v.w;
        }
        __syncthreads();
        #pragma unroll
        for (int kk = 0; kk < 16; kk++) {
            float a[8], b[8];
            #pragma unroll
            for (int i = 0; i < 8; i++) a[i] = As[kk][ty*8+i];
            #pragma unroll
            for (int j = 0; j < 8; j++) b[j] = Bs[kk][tx + 16*j];
            #pragma unroll
            for (int i = 0; i < 8; i++)
                #pragma unroll
                for (int j = 0; j < 8; j++) acc[i][j] += a[i]*b[j];
        }
        __syncthreads();
    }
    #pragma unroll
    for (int i = 0; i < 8; i++)
        #pragma unroll
        for (int j = 0; j < 8; j++)
            C[(size_t)(bm+ty*8+i)*N + bn + tx + 16*j] = acc[i][j];
}

// ---------------- M init ----------------
__global__ void k_minit(const float* __restrict__ M0) {
    size_t idx = (size_t)blockIdx.x*256 + threadIdx.x;
    if (idx >= (size_t)2*B_*KVD*DM) return;
    size_t m = idx / ((size_t)B_*KVD*DM);
    size_t r = idx % ((size_t)KVD*DM);
    g_M[idx] = M0[m*((size_t)KVD*DM) + r];
}

// ---------------- persistent delta-memory scan (8 blocks, ci loop inside) ---
__global__ __launch_bounds__(512) void mem_scan(
    const float* __restrict__ x,
    const float* __restrict__ ew, const float* __restrict__ eb,
    const float* __restrict__ aw, const float* __restrict__ ab,
    const float* __restrict__ gw, const float* __restrict__ gb)
{
    int b = blockIdx.x, m = blockIdx.y;
    int tid = threadIdx.x, w = tid >> 5, lane = tid & 31;
    float* M = g_M + ((size_t)(m*B_ + b))*KVD*DM;

    __shared__ float inorm[CH];
    __shared__ float km[DM];
    __shared__ float vt[KVD];
    __shared__ float err[KVD];
    __shared__ float red[16];
    __shared__ float sh[4];
    __shared__ float As[16][68];
    __shared__ float Bs[16][260];

    for (int ci = 0; ci < NC; ci++) {
        const float* c = x + ((size_t)b*S_ + (size_t)ci*CH)*DM;
        float* outbuf = (m == 0 ? g_kmem : g_vmem) + ((size_t)b*S_ + (size_t)ci*CH)*KVD;

        __syncthreads();
        if (tid < 2) sh[tid] = 0.f;
        __syncthreads();

        // Phase 0: per-token norms + hyperparam sigmoid sums
        for (int t = w; t < CH; t += 16) {
            const float* row = c + (size_t)t*DM;
            float sq = 0.f, de = 0.f, da = 0.f;
            for (int d = lane; d < DM; d += 32) {
                float v = row[d];
                sq += v*v;
                de += v*ew[m*DM + d];
                da += v*aw[m*DM + d];
            }
            #pragma unroll
            for (int off = 16; off; off >>= 1) {
                sq += __shfl_xor_sync(0xffffffffu, sq, off);
                de += __shfl_xor_sync(0xffffffffu, de, off);
                da += __shfl_xor_sync(0xffffffffu, da, off);
            }
            if (lane == 0) {
                inorm[t] = 1.f / fmaxf(sqrtf(sq), 1e-5f);
                atomicAdd(&sh[0], 1.f/(1.f + expf(-(de + eb[m]))));
                atomicAdd(&sh[1], 1.f/(1.f + expf(-(da + ab[m]))));
            }
        }
        __syncthreads();

        // kmean
        for (int d = tid; d < DM; d += 512) {
            float s = 0.f;
            for (int t = 0; t < CH; t++) s += c[(size_t)t*DM + d] * inorm[t];
            km[d] = s * (1.f/64.f);
        }
        __syncthreads();

        // Phase 1: tiled retrieval out[64t][256o] = c @ M^T (pre-update M)
        float acc[8][8];
        #pragma unroll
        for (int i = 0; i < 8; i++)
            #pragma unroll
            for (int j = 0; j < 8; j++) acc[i][j] = 0.f;
        int ty = (tid >> 5) & 7, tx = tid & 31;
        for (int k0 = 0; k0 < DM; k0 += 16) {
            if (tid < 256) {
                int t = tid >> 2, q = tid & 3;
                float4 v = *reinterpret_cast<const float4*>(&c[(size_t)t*DM + k0 + q*4]);
                As[q*4+0][t] = v.x; As[q*4+1][t] = v.y;
                As[q*4+2][t] = v.z; As[q*4+3][t] = v.w;
            }
            #pragma unroll
            for (int it = 0; it < 2; it++) {
                int idx = tid + it*512;
                int o = idx >> 2, q = idx & 3;
                float4 v = *reinterpret_cast<const float4*>(&M[(size_t)o*DM + k0 + q*4]);
                Bs[q*4+0][o] = v.x; Bs[q*4+1][o] = v.y;
                Bs[q*4+2][o] = v.z; Bs[q*4+3][o] = v.w;
            }
            __syncthreads();
            if (tid < 256) {
                #pragma unroll
                for (int k = 0; k < 16; k++) {
                    float a[8], bb[8];
                    #pragma unroll
                    for (int i = 0; i < 8; i++) a[i] = As[k][ty*8+i];
                    #pragma unroll
                    for (int j = 0; j < 8; j++) bb[j] = Bs[k][tx + 32*j];
                    #pragma unroll
                    for (int i = 0; i < 8; i++)
                        #pragma unroll
                        for (int j = 0; j < 8; j++) acc[i][j] += a[i]*bb[j];
                }
            }
            __syncthreads();
        }
        if (tid < 256) {
            #pragma unroll
            for (int i = 0; i < 8; i++)
                #pragma unroll
                for (int j = 0; j < 8; j++)
                    outbuf[(size_t)(ty*8+i)*KVD + tx + 32*j] = acc[i][j];
        }
        __syncthreads();
        if (tid < KVD) {
            float s = 0.f;
            for (int t = 0; t < CH; t++) s += outbuf[(size_t)t*KVD + tid];
            vt[tid] = s * (1.f/64.f);
        }
        __syncthreads();

        // Phase 3: err = vt - M.kmean, gate
        for (int oo = 0; oo < 16; oo++) {
            int o = w*16 + oo;
            const float* Mrow = M + (size_t)o*DM;
            float s = 0.f;
            for (int d = lane; d < DM; d += 32) s += Mrow[d]*km[d];
            #pragma unroll
            for (int off = 16; off; off >>= 1) s += __shfl_xor_sync(0xffffffffu, s, off);
            if (lane == 0) err[o] = vt[o] - s;
        }
        {
            float gp = km[tid]*gw[m*DM + tid] + km[tid+512]*gw[m*DM + tid + 512];
            #pragma unroll
            for (int off = 16; off; off >>= 1) gp += __shfl_xor_sync(0xffffffffu, gp, off);
            if (lane == 0) red[w] = gp;
        }
        __syncthreads();
        if (tid == 0) {
            float gdot = 0.f;
            for (int ww = 0; ww < 16; ww++) gdot += red[ww];
            sh[2] = 1.f/(1.f + expf(-(gdot + gb[m])));
        }
        __syncthreads();
        float gt = sh[2];
        float eta = 0.2f * sh[0] * (1.f/64.f);
        float al  = 0.5f + 0.5f * sh[1] * (1.f/64.f);
        float aco = gt*al + 1.f - gt;
        float bco = gt*eta;

        // Phase 4: update (float4) + Frobenius clamp
        float ss = 0.f;
        float4* M4 = reinterpret_cast<float4*>(M);
        for (int i4 = tid; i4 < KVD*DM/4; i4 += 512) {
            int o = i4 >> 8;
            int db = (i4 & 255) * 4;
            float eo = bco * err[o];
            float4 mv = M4[i4];
            mv.x = aco*mv.x + eo*km[db+0];
            mv.y = aco*mv.y + eo*km[db+1];
            mv.z = aco*mv.z + eo*km[db+2];
            mv.w = aco*mv.w + eo*km[db+3];
            M4[i4] = mv;
            ss += mv.x*mv.x + mv.y*mv.y + mv.z*mv.z + mv.w*mv.w;
        }
        #pragma unroll
        for (int off = 16; off; off >>= 1) ss += __shfl_xor_sync(0xffffffffu, ss, off);
        if (lane == 0) red[w] = ss;
        __syncthreads();
        if (tid == 0) {
            float tot = 0.f;
            for (int ww = 0; ww < 16; ww++) tot += red[ww];
            sh[3] = fminf(30.f/(sqrtf(tot) + 1e-6f), 1.f);
        }
        __syncthreads();
        float sc = sh[3];
        if (sc != 1.f)
            for (int i4 = tid; i4 < KVD*DM/4; i4 += 512) {
                float4 mv = M4[i4];
                mv.x *= sc; mv.y *= sc; mv.z *= sc; mv.w *= sc;
                M4[i4] = mv;
            }
    }
}

// ---------------- q build with RoPE (table) ----------------
__global__ void q_build() {
    size_t idx = (size_t)blockIdx.x*256 + threadIdx.x;
    if (idx >= (size_t)TOK*DM) return;
    int col = (int)(idx & (DM-1));
    size_t t = idx >> 10;
    int b = (int)(t >> 11), pos = (int)(t & 2047);
    int h = col >> 6, d = col & 63;
    float qc = g_xq[idx];
    int pd = (d < 32) ? d + 32 : d - 32;
    float qp = g_xq[(t << 10) + h*64 + pd];
    float rot = (d < 32) ? -qp : qp;
    float cs = g_cos[pos*32 + (d & 31)], sn = g_sin[pos*32 + (d & 31)];
    g_q[(((size_t)b*NH + h)*S_ + pos)*HD + d] = qc*cs + rot*sn;
}

// ---------------- k build ----------------
__global__ void k_build() {
    size_t idx = (size_t)blockIdx.x*256 + threadIdx.x;
    if (idx >= (size_t)TOK*KVD) return;
    int o = (int)(idx & (KVD-1));
    size_t t = idx >> 8;
    int b = (int)(t >> 11), pos = (int)(t & 2047);
    int kv = o >> 6, d = o & 63;
    float kc = g_xk[idx] + g_kmem[idx];
    int pd = (d < 32) ? d + 32 : d - 32;
    size_t pidx = (t << 8) + kv*64 + pd;
    float kp = g_xk[pidx] + g_kmem[pidx];
    float rot = (d < 32) ? -kp : kp;
    float cs = g_cos[pos*32 + (d & 31)], sn = g_sin[pos*32 + (d & 31)];
    g_k[(((size_t)b*NKV + kv)*S_ + pos)*HD + d] = kc*cs + rot*sn;
}

// ---------------- v build ----------------
__global__ void v_build() {
    size_t idx = (size_t)blockIdx.x*256 + threadIdx.x;
    if (idx >= (size_t)TOK*KVD) return;
    int o = (int)(idx & (KVD-1));
    size_t t = idx >> 8;
    int b = (int)(t >> 11), pos = (int)(t & 2047);
    int kv = o >> 6, d = o & 63;
    g_v[(((size_t)b*NKV + kv)*S_ + pos)*HD + d] = g_xv[idx] + g_vmem[idx];
}

// ---------------- causal flash attention, GEMM-style 4x4 register tiling ----
// 256 thr: tx=tid&15 (4 keys / 4 out-dims), ty=tid>>4 (4 queries).
__global__ __launch_bounds__(256) void k_attn() {
    extern __shared__ float sm[];
    float* Qs = sm;              // 64*64
    float* Kt = Qs + 4096;       // 64*68 (transposed: Kt[d][k])
    float* Vs = Kt + 64*68;      // 64*64
    float* Ps = Vs + 4096;       // 64*68
    int qt = blockIdx.x, h = blockIdx.y, b = blockIdx.z;
    int tid = threadIdx.x;
    int tx = tid & 15, ty = tid >> 4;
    int q0 = ty*4, k0 = tx*4;

    // load Q tile (scaled by 1/8)
    const float* Qbase = g_q + (((size_t)b*NH + h)*S_ + (size_t)qt*64)*HD;
    #pragma unroll
    for (int it = 0; it < 4; it++) {
        int lin = tid + it*256;
        int r = lin >> 4, c = (lin & 15)*4;
        float4 v = *reinterpret_cast<const float4*>(&Qbase[(size_t)r*HD + c]);
        Qs[r*64+c+0] = v.x*0.125f; Qs[r*64+c+1] = v.y*0.125f;
        Qs[r*64+c+2] = v.z*0.125f; Qs[r*64+c+3] = v.w*0.125f;
    }

    float O[4][4];
    float mrun[4], lrun[4];
    #pragma unroll
    for (int i = 0; i < 4; i++) {
        mrun[i] = -1e30f; lrun[i] = 0.f;
        #pragma unroll
        for (int j = 0; j < 4; j++) O[i][j] = 0.f;
    }

    int kvh = h >> 2;
    const float* Kbase = g_k + ((size_t)b*NKV + kvh)*S_*HD;
    const float* Vbase = g_v + ((size_t)b*NKV + kvh)*S_*HD;

    for (int kt = 0; kt <= qt; kt++) {
        __syncthreads();   // prior PV reads of Vs done; Qs ready on first iter
        // load K transposed
        {
            int r = tid >> 2, q = tid & 3;
            const float* krow = &Kbase[(size_t)(kt*64 + r)*HD + q*16];
            #pragma unroll
            for (int c4 = 0; c4 < 4; c4++) {
                float4 v = *reinterpret_cast<const float4*>(&krow[c4*4]);
                int d = q*16 + c4*4;
                Kt[(d+0)*68 + r] = v.x; Kt[(d+1)*68 + r] = v.y;
                Kt[(d+2)*68 + r] = v.z; Kt[(d+3)*68 + r] = v.w;
            }
        }
        // load V
        #pragma unroll
        for (int it = 0; it < 4; it++) {
            int lin = tid + it*256;
            int r = lin >> 4, c = (lin & 15)*4;
            *reinterpret_cast<float4*>(&Vs[r*64+c]) =
                *reinterpret_cast<const float4*>(&Vbase[(size_t)(kt*64 + r)*HD + c]);
        }
        __syncthreads();

        // S = Q @ K^T  (4x4 per thread)
        float acc[4][4];
        #pragma unroll
        for (int i = 0; i < 4; i++)
            #pragma unroll
            for (int j = 0; j < 4; j++) acc[i][j] = 0.f;
        #pragma unroll 8
        for (int d = 0; d < 64; d++) {
            float a[4];
            #pragma unroll
            for (int i = 0; i < 4; i++) a[i] = Qs[(q0+i)*64 + d];
            float4 bv = *reinterpret_cast<const float4*>(&Kt[d*68 + k0]);
            #pragma unroll
            for (int i = 0; i < 4; i++) {
                acc[i][0] += a[i]*bv.x; acc[i][1] += a[i]*bv.y;
                acc[i][2] += a[i]*bv.z; acc[i][3] += a[i]*bv.w;
            }
        }
        // causal mask (within diagonal tile)
        if (kt == qt) {
            #pragma unroll
            for (int i = 0; i < 4; i++)
                #pragma unroll
                for (int j = 0; j < 4; j++)
                    if (k0 + j > q0 + i) acc[i][j] = -1e30f;
        }
        // online softmax per row (16 lanes per row; xor offsets stay in-warp)
        #pragma unroll
        for (int i = 0; i < 4; i++) {
            float rmax = fmaxf(fmaxf(acc[i][0], acc[i][1]), fmaxf(acc[i][2], acc[i][3]));
            #pragma unroll
            for (int off = 1; off < 16; off <<= 1)
                rmax = fmaxf(rmax, __shfl_xor_sync(0xffffffffu, rmax, off));
            float tmax = fmaxf(mrun[i], rmax);
            float corr = __expf(mrun[i] - tmax);
            mrun[i] = tmax;
            float p0 = __expf(acc[i][0] - tmax), p1 = __expf(acc[i][1] - tmax);
            float p2 = __expf(acc[i][2] - tmax), p3 = __expf(acc[i][3] - tmax);
            float rsum = p0 + p1 + p2 + p3;
            #pragma unroll
            for (int off = 1; off < 16; off <<= 1)
                rsum += __shfl_xor_sync(0xffffffffu, rsum, off);
            lrun[i] = lrun[i]*corr + rsum;
            #pragma unroll
            for (int j = 0; j < 4; j++) O[i][j] *= corr;
            Ps[(q0+i)*68 + k0+0] = p0; Ps[(q0+i)*68 + k0+1] = p1;
            Ps[(q0+i)*68 + k0+2] = p2; Ps[(q0+i)*68 + k0+3] = p3;
        }
        __syncthreads();

        // O += P @ V  (4 queries x 4 out-dims, d0 = tx*4)
        #pragma unroll 8
        for (int kk = 0; kk < 64; kk++) {
            float a[4];
            #pragma unroll
            for (int i = 0; i < 4; i++) a[i] = Ps[(q0+i)*68 + kk];
            float4 bv = *reinterpret_cast<const float4*>(&Vs[kk*64 + k0]);
            #pragma unroll
            for (int i = 0; i < 4; i++) {
                O[i][0] += a[i]*bv.x; O[i][1] += a[i]*bv.y;
                O[i][2] += a[i]*bv.z; O[i][3] += a[i]*bv.w;
            }
        }
    }
    #pragma unroll
    for (int i = 0; i < 4; i++) {
        float inv = 1.f / lrun[i];
        float4 v = make_float4(O[i][0]*inv, O[i][1]*inv, O[i][2]*inv, O[i][3]*inv);
        *reinterpret_cast<float4*>(
            &g_ao[((size_t)(b*S_ + qt*64 + q0 + i))*DM + h*HD + k0]) = v;
    }
}

// ---------------- host launch with size-based input routing ----------------
extern "C" void kernel_launch(void* const* d_in, const int* in_sizes, int n_in,
                              void* d_out, int out_size) {
    (void)out_size;
    const float *x = 0, *Wq = 0, *Wk = 0, *Wv = 0, *Wo = 0, *M0 = 0;
    const float *ew = 0, *eb = 0, *aw = 0, *ab = 0, *gw = 0, *gb = 0;
    int n1M = 0, n256K = 0, n2K = 0, nB = 0;
    for (int i = 0; i < n_in; i++) {
        const float* p = (const float*)d_in[i];
        switch (in_sizes[i]) {
            case 8388608: x = p; break;
            case  524288: M0 = p; break;
            case 1048576: if (n1M++ == 0) Wq = p; else Wo = p; break;
            case  262144: if (n256K++ == 0) Wk = p; else Wv = p; break;
            case    2048: { if (n2K == 0) ew = p; else if (n2K == 1) aw = p; else gw = p; n2K++; } break;
            case       2: { if (nB == 0) eb = p; else if (nB == 1) ab = p; else gb = p; nB++; } break;
            default: break;
        }
    }
    float* out = (float*)d_out;

    float *pXq = 0, *pXk = 0, *pXv = 0, *pAo = 0;
    cudaGetSymbolAddress((void**)&pXq, g_xq);
    cudaGetSymbolAddress((void**)&pXk, g_xk);
    cudaGetSymbolAddress((void**)&pXv, g_xv);
    cudaGetSymbolAddress((void**)&pAo, g_ao);

    cudaFuncSetAttribute(k_attn, cudaFuncAttributeMaxDynamicSharedMemorySize, 70000);

    k_trig<<<(S_*32 + 255)/256, 256>>>();

    // projections
    k_sgemm<<<dim3(DM/128,  TOK/128), 256>>>(x, Wq, pXq, TOK, DM,  DM);
    k_sgemm<<<dim3(KVD/128, TOK/128), 256>>>(x, Wk, pXk, TOK, KVD, DM);
    k_sgemm<<<dim3(KVD/128, TOK/128), 256>>>(x, Wv, pXv, TOK, KVD, DM);

    // memory scan (single persistent kernel)
    k_minit<<<(int)(((size_t)2*B_*KVD*DM + 255)/256), 256>>>(M0);
    mem_scan<<<dim3(B_, 2), 512>>>(x, ew, eb, aw, ab, gw, gb);

    // q/k/v assembly + rope
    q_build<<<(int)(((size_t)TOK*DM  + 255)/256), 256>>>();
    k_build<<<(int)(((size_t)TOK*KVD + 255)/256), 256>>>();
    v_build<<<(int)(((size_t)TOK*KVD + 255)/256), 256>>>();

    // attention + output projection
    k_attn<<<dim3(S_/64, NH, B_), 256, 70000>>>();
    k_sgemm<<<dim3(DM/128, TOK/128), 256>>>(pAo, Wo, out, TOK, DM, DM);
}

// round 11
// speedup vs baseline: 99.3849x; 3.0900x over previous
#include <cuda_runtime.h>
#include <math.h>

#define B_  4
#define S_  2048
#define DM  1024
#define NH  16
#define NKV 4
#define HD  64
#define KVD 256
#define CH  64
#define NC  32
#define TOK (B_*S_)
#define NCOLS 2048   // Wq(1024)|Wk(256)|Wv(256)|M0[0]^T(256)|M0[1]^T(256)

// ---------------- device scratch (static; no allocation) ----------------
__device__ float g_Wcat[(size_t)DM*NCOLS];
__device__ float g_qkv[(size_t)TOK*NCOLS];
__device__ float g_cmean[B_*NC*DM];
__device__ float g_kmean[B_*NC*DM];
__device__ float g_inorm[TOK];
__device__ float g_eta[B_*2*NC];
__device__ float g_alpha[B_*2*NC];
__device__ float g_mk0[B_*2*NC*KVD];
__device__ float g_mv0[B_*2*NC*KVD];
__device__ float g_m0n2[2];
__device__ float g_U[B_*2*NC*KVD];
__device__ float g_Qret[B_*2*NC];
__device__ float g_Wret[B_*2*NC*NC];
__device__ float g_D[(size_t)TOK*NC];
__device__ float g_q[(size_t)B_*NH*S_*HD];
__device__ float g_k[(size_t)B_*NKV*S_*HD];
__device__ float g_v[(size_t)B_*NKV*S_*HD];
__device__ float g_ao[(size_t)TOK*DM];
__device__ float g_cos[S_*32];
__device__ float g_sin[S_*32];

#define LOG_ROPE_BASE 13.122363377404331

// ---------------- RoPE trig table ----------------
__global__ void k_trig() {
    int idx = blockIdx.x*256 + threadIdx.x;
    if (idx >= S_*32) return;
    int pos = idx >> 5, fi = idx & 31;
    double f = exp(-(double)fi * (LOG_ROPE_BASE/32.0));
    double ds, dc;
    sincos((double)pos * f, &ds, &dc);
    g_cos[idx] = (float)dc;
    g_sin[idx] = (float)ds;
}

// ---------------- weight concat: [Wq | Wk | Wv | M0_0^T | M0_1^T] ----------
__global__ __launch_bounds__(256) void k_prep(const float* __restrict__ Wq,
                                              const float* __restrict__ Wk,
                                              const float* __restrict__ Wv,
                                              const float* __restrict__ M0) {
    size_t idx = (size_t)blockIdx.x*256 + threadIdx.x;
    if (idx >= (size_t)DM*NCOLS) return;
    int d = (int)(idx / NCOLS), c = (int)(idx % NCOLS);
    float v;
    if (c < 1024)       v = Wq[(size_t)d*1024 + c];
    else if (c < 1280)  v = Wk[(size_t)d*256 + (c-1024)];
    else if (c < 1536)  v = Wv[(size_t)d*256 + (c-1280)];
    else if (c < 1792)  v = M0[(size_t)(c-1536)*DM + d];
    else                v = M0[(size_t)(KVD + (c-1792))*DM + d];
    g_Wcat[idx] = v;
}

// ---------------- fast SGEMM: C[M,N] = A[M,K] @ B[K,N], 128x128x16 ----------
__global__ __launch_bounds__(256) void k_sgemm(const float* __restrict__ A,
                                               const float* __restrict__ B,
                                               float* __restrict__ C,
                                               int M, int N, int K) {
    __shared__ float As[16][128];
    __shared__ float Bs[16][132];
    int tid = threadIdx.x;
    int bm = blockIdx.y * 128, bn = blockIdx.x * 128;
    int tx = tid & 15, ty = tid >> 4;
    float acc[8][8];
    #pragma unroll
    for (int i = 0; i < 8; i++)
        #pragma unroll
        for (int j = 0; j < 8; j++) acc[i][j] = 0.f;
    for (int k0 = 0; k0 < K; k0 += 16) {
        #pragma unroll
        for (int it = 0; it < 2; it++) {
            int idx = tid + it*256;
            int row = idx >> 2, q = idx & 3;
            float4 v = *reinterpret_cast<const float4*>(&A[(size_t)(bm+row)*K + k0 + q*4]);
            As[q*4+0][row] = v.x; As[q*4+1][row] = v.y;
            As[q*4+2][row] = v.z; As[q*4+3][row] = v.w;
        }
        #pragma unroll
        for (int it = 0; it < 2; it++) {
            int idx = tid + it*256;
            int row = idx >> 5, q = idx & 31;
            float4 v = *reinterpret_cast<const float4*>(&B[(size_t)(k0+row)*N + bn + q*4]);
            Bs[row][q*4+0] = v.x; Bs[row][q*4+1] = v.y;
            Bs[row][q*4+2] = v.z; Bs[row][q*4+3] = v.w;
        }
        __syncthreads();
        #pragma unroll
        for (int kk = 0; kk < 16; kk++) {
            float a[8], b[8];
            #pragma unroll
            for (int i = 0; i < 8; i++) a[i] = As[kk][ty*8+i];
            #pragma unroll
            for (int j = 0; j < 8; j++) b[j] = Bs[kk][tx + 16*j];
            #pragma unroll
            for (int i = 0; i < 8; i++)
                #pragma unroll
                for (int j = 0; j < 8; j++) acc[i][j] += a[i]*b[j];
        }
        __syncthreads();
    }
    #pragma unroll
    for (int i = 0; i < 8; i++)
        #pragma unroll
        for (int j = 0; j < 8; j++)
            C[(size_t)(bm+ty*8+i)*N + bn + tx + 16*j] = acc[i][j];
}

// ---------------- per-chunk stats (cmean, kmean, inorm, eta, alpha) --------
__global__ __launch_bounds__(256) void k_chunkstats(const float* __restrict__ x,
                                                    const float* __restrict__ ew,
                                                    const float* __restrict__ eb,
                                                    const float* __restrict__ aw,
                                                    const float* __restrict__ ab) {
    int b = blockIdx.x >> 5, i = blockIdx.x & 31;
    const float* cx = x + ((size_t)(b*S_) + i*CH) * DM;
    __shared__ float inorm[CH];
    __shared__ float wacc[8][4];
    int tid = threadIdx.x, w = tid >> 5, lane = tid & 31;
    float a0 = 0.f, a1 = 0.f, a2 = 0.f, a3 = 0.f;
    for (int t = w; t < CH; t += 8) {
        const float* row = cx + (size_t)t * DM;
        float sq = 0.f, d0 = 0.f, d1 = 0.f, d2 = 0.f, d3 = 0.f;
        for (int d = lane; d < DM; d += 32) {
            float v = row[d];
            sq += v*v;
            d0 += v*ew[d];    d1 += v*ew[DM+d];
            d2 += v*aw[d];    d3 += v*aw[DM+d];
        }
        #pragma unroll
        for (int off = 16; off; off >>= 1) {
            sq += __shfl_xor_sync(0xffffffffu, sq, off);
            d0 += __shfl_xor_sync(0xffffffffu, d0, off);
            d1 += __shfl_xor_sync(0xffffffffu, d1, off);
            d2 += __shfl_xor_sync(0xffffffffu, d2, off);
            d3 += __shfl_xor_sync(0xffffffffu, d3, off);
        }
        if (lane == 0) {
            float in = 1.f / fmaxf(sqrtf(sq), 1e-5f);
            inorm[t] = in;
            g_inorm[b*S_ + i*CH + t] = in;
            a0 += 1.f/(1.f + expf(-(d0 + eb[0])));
            a1 += 1.f/(1.f + expf(-(d1 + eb[1])));
            a2 += 1.f/(1.f + expf(-(d2 + ab[0])));
            a3 += 1.f/(1.f + expf(-(d3 + ab[1])));
        }
    }
    if (lane == 0) { wacc[w][0]=a0; wacc[w][1]=a1; wacc[w][2]=a2; wacc[w][3]=a3; }
    __syncthreads();
    if (tid == 0) {
        float e0=0.f,e1=0.f,l0=0.f,l1=0.f;
        for (int ww = 0; ww < 8; ww++) { e0+=wacc[ww][0]; e1+=wacc[ww][1]; l0+=wacc[ww][2]; l1+=wacc[ww][3]; }
        g_eta  [(b*2+0)*NC+i] = 0.2f * e0 * (1.f/64.f);
        g_eta  [(b*2+1)*NC+i] = 0.2f * e1 * (1.f/64.f);
        g_alpha[(b*2+0)*NC+i] = 0.5f + 0.5f * l0 * (1.f/64.f);
        g_alpha[(b*2+1)*NC+i] = 0.5f + 0.5f * l1 * (1.f/64.f);
    }
    __syncthreads();
    for (int d = tid; d < DM; d += 256) {
        float sc = 0.f, sk = 0.f;
        for (int t = 0; t < CH; t++) {
            float v = cx[(size_t)t*DM + d];
            sc += v;
            sk += v * inorm[t];
        }
        g_cmean[(b*NC+i)*DM + d] = sc * (1.f/64.f);
        g_kmean[(b*NC+i)*DM + d] = sk * (1.f/64.f);
    }
}

// ---------------- ||M0||^2 ----------------
__global__ __launch_bounds__(256) void k_m0norm(const float* __restrict__ M0) {
    int m = blockIdx.x;
    __shared__ float red[8];
    float s = 0.f;
    const float* p = M0 + (size_t)m * KVD * DM;
    for (int idx = threadIdx.x; idx < KVD*DM; idx += 256) { float v = p[idx]; s += v*v; }
    #pragma unroll
    for (int off = 16; off; off >>= 1) s += __shfl_xor_sync(0xffffffffu, s, off);
    int w = threadIdx.x >> 5, lane = threadIdx.x & 31;
    if (lane == 0) red[w] = s;
    __syncthreads();
    if (threadIdx.x == 0) {
        float t = 0.f;
        for (int ww = 0; ww < 8; ww++) t += red[ww];
        g_m0n2[m] = t;
    }
}

// ---------------- M0@cmean, M0@kmean from qkv columns ----------------
__global__ __launch_bounds__(256) void k_m0proj() {
    int b = blockIdx.x >> 5, i = blockIdx.x & 31;
    int tid = threadIdx.x;
    const float* base = g_qkv + (size_t)(b*S_ + i*CH)*NCOLS;
    const float* inr = g_inorm + b*S_ + i*CH;
    for (int p = tid; p < 512; p += 256) {
        int col = 1536 + p;
        float sc = 0.f, sk = 0.f;
        for (int t = 0; t < CH; t++) {
            float v = base[(size_t)t*NCOLS + col];
            sc += v;
            sk += v * inr[t];
        }
        int m = p >> 8, o = p & 255;
        g_mv0[((b*2+m)*NC+i)*KVD + o] = sc * (1.f/64.f);
        g_mk0[((b*2+m)*NC+i)*KVD + o] = sk * (1.f/64.f);
    }
}

// ---------------- sequential low-rank recurrence (8 blocks, tiny) ----------
__global__ __launch_bounds__(256) void k_recur(const float* __restrict__ gw,
                                               const float* __restrict__ gb) {
    int b = blockIdx.x, m = blockIdx.y;
    __shared__ float kks[NC*NC];
    __shared__ float kcs[NC*NC];
    __shared__ float errs[NC*KVD];
    __shared__ float gates[NC], Wcur[NC];
    __shared__ float red1[8], red2[8], bc[2];
    int tid = threadIdx.x, w = tid >> 5, lane = tid & 31;
    const float* kmb = g_kmean + (size_t)b*NC*DM;
    const float* cmb = g_cmean + (size_t)b*NC*DM;
    // gram matrices: kks[i][j] = km_i . km_j ; kcs[i][j] = km_j . cmean_i
    for (int p = w; p < 2*NC*NC; p += 8) {
        int pi = (p < NC*NC) ? p : p - NC*NC;
        int i = pi >> 5, j = pi & 31;
        const float* u  = kmb + (size_t)j*DM;
        const float* vv = (p < NC*NC) ? (kmb + (size_t)i*DM) : (cmb + (size_t)i*DM);
        float s = 0.f;
        for (int d = lane; d < DM; d += 32) s += u[d]*vv[d];
        #pragma unroll
        for (int off = 16; off; off >>= 1) s += __shfl_xor_sync(0xffffffffu, s, off);
        if (lane == 0) { if (p < NC*NC) kks[i*NC+j] = s; else kcs[i*NC+j] = s; }
    }
    for (int g = w; g < NC; g += 8) {
        const float* u = kmb + (size_t)g*DM;
        float s = 0.f;
        for (int d = lane; d < DM; d += 32) s += u[d]*gw[m*DM + d];
        #pragma unroll
        for (int off = 16; off; off >>= 1) s += __shfl_xor_sync(0xffffffffu, s, off);
        if (lane == 0) gates[g] = 1.f/(1.f + expf(-(s + gb[m])));
    }
    if (tid < NC) Wcur[tid] = 0.f;
    __syncthreads();

    float Q = 1.f, N2 = g_m0n2[m];
    int bm = b*2 + m;
    int o = tid;   // 256 == KVD
    for (int i = 0; i < NC; i++) {
        float vt = Q * g_mv0[(bm*NC+i)*KVD + o];
        float mk = Q * g_mk0[(bm*NC+i)*KVD + o];
        for (int j = 0; j < i; j++) {
            float we = Wcur[j] * errs[j*KVD + o];
            vt += we * kcs[i*NC+j];
            mk += we * kks[i*NC+j];
        }
        float e = vt - mk;
        errs[i*KVD + o] = e;
        g_U[(bm*NC+i)*KVD + o] = e;
        float p1 = mk*e, p2 = e*e;
        #pragma unroll
        for (int off = 16; off; off >>= 1) {
            p1 += __shfl_xor_sync(0xffffffffu, p1, off);
            p2 += __shfl_xor_sync(0xffffffffu, p2, off);
        }
        if (lane == 0) { red1[w] = p1; red2[w] = p2; }
        __syncthreads();
        if (tid == 0) {
            float s1 = 0.f, s2 = 0.f;
            for (int ww = 0; ww < 8; ww++) { s1 += red1[ww]; s2 += red2[ww]; }
            bc[0] = s1; bc[1] = s2;
        }
        __syncthreads();
        float dot1 = bc[0], errsq = bc[1];
        float gt = gates[i];
        float eta = g_eta[bm*NC+i], al = g_alpha[bm*NC+i];
        float a  = gt*al + 1.f - gt;
        float b0 = gt*eta;
        float m2 = a*a*N2 + 2.f*a*b0*dot1 + b0*b0*errsq*kks[i*NC+i];
        float s  = fminf(30.f/(sqrtf(m2) + 1e-6f), 1.f);
        if (tid < NC) g_Wret[(bm*NC+i)*NC + tid] = (tid < i) ? Wcur[tid] : 0.f;
        if (tid == 0) g_Qret[bm*NC+i] = Q;
        __syncthreads();
        if (tid < NC) { if (tid < i) Wcur[tid] *= s*a; else if (tid == i) Wcur[tid] = s*b0; }
        Q *= s*a;
        N2 = s*s*m2;
        __syncthreads();
    }
}

// ---------------- D[b,t,j] = x_t . kmean_j ----------------
__global__ __launch_bounds__(256) void k_dtok(const float* __restrict__ x) {
    __shared__ float xs[32][128];
    __shared__ float ks[32][129];
    int b = blockIdx.y, t0 = blockIdx.x * 32;
    int tid = threadIdx.x;
    int tl = tid >> 5, j = tid & 31;
    float acc[4] = {0.f, 0.f, 0.f, 0.f};
    for (int d0 = 0; d0 < DM; d0 += 128) {
        #pragma unroll
        for (int it = 0; it < 4; it++) {
            int lin = tid + it*256;
            int r = lin >> 5, q = lin & 31;
            float4 xv = *reinterpret_cast<const float4*>(&x[((size_t)(b*S_) + t0 + r)*DM + d0 + q*4]);
            *reinterpret_cast<float4*>(&xs[r][q*4]) = xv;
            float4 kv = *reinterpret_cast<const float4*>(&g_kmean[((size_t)(b*NC) + r)*DM + d0 + q*4]);
            ks[r][q*4+0] = kv.x; ks[r][q*4+1] = kv.y; ks[r][q*4+2] = kv.z; ks[r][q*4+3] = kv.w;
        }
        __syncthreads();
        #pragma unroll
        for (int tt = 0; tt < 4; tt++) {
            int t = tl + tt*8;
            float s = 0.f;
            #pragma unroll 16
            for (int d = 0; d < 128; d++) s += xs[t][d]*ks[j][d];
            acc[tt] += s;
        }
        __syncthreads();
    }
    #pragma unroll
    for (int tt = 0; tt < 4; tt++)
        g_D[((size_t)(b*S_) + t0 + tl + tt*8)*NC + j] = acc[tt];
}

// ---------------- build q(rope), k(mem+rope), v(mem) ----------------
__global__ __launch_bounds__(256) void k_epilogue() {
    int blk = blockIdx.x;
    int b = blk >> 11, pos = blk & 2047;
    int i = pos >> 6;
    int tid = threadIdx.x;
    __shared__ float wd0[NC], wd1[NC], kbuf[KVD];
    if (tid < 32) {
        float Dv = g_D[((size_t)(b*S_) + pos)*NC + tid];
        wd0[tid] = g_Wret[((b*2+0)*NC+i)*NC + tid] * Dv;
        wd1[tid] = g_Wret[((b*2+1)*NC+i)*NC + tid] * Dv;
    }
    __syncthreads();
    const float* row = g_qkv + (size_t)(b*S_ + pos) * NCOLS;
    float q0 = g_Qret[(b*2+0)*NC+i], q1 = g_Qret[(b*2+1)*NC+i];
    int o = tid;
    float kval = row[1024 + o] + q0 * row[1536 + o];
    float vval = row[1280 + o] + q1 * row[1792 + o];
    const float* U0 = g_U + (size_t)(b*2+0)*NC*KVD;
    const float* U1 = g_U + (size_t)(b*2+1)*NC*KVD;
    #pragma unroll 8
    for (int j = 0; j < NC; j++) {
        kval += wd0[j] * U0[j*KVD + o];
        vval += wd1[j] * U1[j*KVD + o];
    }
    kbuf[o] = kval;
    __syncthreads();
    int d = o & 63, kv = o >> 6;
    float cs = g_cos[pos*32 + (d & 31)], sn = g_sin[pos*32 + (d & 31)];
    float rot = (d < 32) ? -kbuf[kv*64 + d + 32] : kbuf[kv*64 + d - 32];
    size_t kidx = (((size_t)(b*NKV) + kv)*S_ + pos)*HD + d;
    g_k[kidx] = kval*cs + rot*sn;
    g_v[kidx] = vval;
    for (int oq = tid; oq < DM; oq += 256) {
        float qv = row[oq];
        int dd = oq & 63, h = oq >> 6;
        float part = row[h*64 + ((dd < 32) ? dd + 32 : dd - 32)];
        float rq = (dd < 32) ? -part : part;
        float c2 = g_cos[pos*32 + (dd & 31)], s2 = g_sin[pos*32 + (dd & 31)];
        g_q[(((size_t)(b*NH) + h)*S_ + pos)*HD + dd] = qv*c2 + rq*s2;
    }
}

// ---------------- causal flash attention, GEMM-style 4x4 register tiling ----
__global__ __launch_bounds__(256) void k_attn() {
    extern __shared__ float sm[];
    float* Qs = sm;              // 64*64
    float* Kt = Qs + 4096;       // 64*68 (transposed)
    float* Vs = Kt + 64*68;      // 64*64
    float* Ps = Vs + 4096;       // 64*68
    int qt = blockIdx.x, h = blockIdx.y, b = blockIdx.z;
    int tid = threadIdx.x;
    int tx = tid & 15, ty = tid >> 4;
    int q0 = ty*4, k0 = tx*4;

    const float* Qbase = g_q + (((size_t)b*NH + h)*S_ + (size_t)qt*64)*HD;
    #pragma unroll
    for (int it = 0; it < 4; it++) {
        int lin = tid + it*256;
        int r = lin >> 4, c = (lin & 15)*4;
        float4 v = *reinterpret_cast<const float4*>(&Qbase[(size_t)r*HD + c]);
        Qs[r*64+c+0] = v.x*0.125f; Qs[r*64+c+1] = v.y*0.125f;
        Qs[r*64+c+2] = v.z*0.125f; Qs[r*64+c+3] = v.w*0.125f;
    }

    float O[4][4];
    float mrun[4], lrun[4];
    #pragma unroll
    for (int i = 0; i < 4; i++) {
        mrun[i] = -1e30f; lrun[i] = 0.f;
        #pragma unroll
        for (int j = 0; j < 4; j++) O[i][j] = 0.f;
    }

    int kvh = h >> 2;
    const float* Kbase = g_k + ((size_t)b*NKV + kvh)*S_*HD;
    const float* Vbase = g_v + ((size_t)b*NKV + kvh)*S_*HD;

    for (int kt = 0; kt <= qt; kt++) {
        __syncthreads();
        {
            int r = tid >> 2, q = tid & 3;
            const float* krow = &Kbase[(size_t)(kt*64 + r)*HD + q*16];
            #pragma unroll
            for (int c4 = 0; c4 < 4; c4++) {
                float4 v = *reinterpret_cast<const float4*>(&krow[c4*4]);
                int d = q*16 + c4*4;
                Kt[(d+0)*68 + r] = v.x; Kt[(d+1)*68 + r] = v.y;
                Kt[(d+2)*68 + r] = v.z; Kt[(d+3)*68 + r] = v.w;
            }
        }
        #pragma unroll
        for (int it = 0; it < 4; it++) {
            int lin = tid + it*256;
            int r = lin >> 4, c = (lin & 15)*4;
            *reinterpret_cast<float4*>(&Vs[r*64+c]) =
                *reinterpret_cast<const float4*>(&Vbase[(size_t)(kt*64 + r)*HD + c]);
        }
        __syncthreads();

        float acc[4][4];
        #pragma unroll
        for (int i = 0; i < 4; i++)
            #pragma unroll
            for (int j = 0; j < 4; j++) acc[i][j] = 0.f;
        #pragma unroll 8
        for (int d = 0; d < 64; d++) {
            float a[4];
            #pragma unroll
            for (int i = 0; i < 4; i++) a[i] = Qs[(q0+i)*64 + d];
            float4 bv = *reinterpret_cast<const float4*>(&Kt[d*68 + k0]);
            #pragma unroll
            for (int i = 0; i < 4; i++) {
                acc[i][0] += a[i]*bv.x; acc[i][1] += a[i]*bv.y;
                acc[i][2] += a[i]*bv.z; acc[i][3] += a[i]*bv.w;
            }
        }
        if (kt == qt) {
            #pragma unroll
            for (int i = 0; i < 4; i++)
                #pragma unroll
                for (int j = 0; j < 4; j++)
                    if (k0 + j > q0 + i) acc[i][j] = -1e30f;
        }
        #pragma unroll
        for (int i = 0; i < 4; i++) {
            float rmax = fmaxf(fmaxf(acc[i][0], acc[i][1]), fmaxf(acc[i][2], acc[i][3]));
            #pragma unroll
            for (int off = 1; off < 16; off <<= 1)
                rmax = fmaxf(rmax, __shfl_xor_sync(0xffffffffu, rmax, off));
            float tmax = fmaxf(mrun[i], rmax);
            float corr = __expf(mrun[i] - tmax);
            mrun[i] = tmax;
            float p0 = __expf(acc[i][0] - tmax), p1 = __expf(acc[i][1] - tmax);
            float p2 = __expf(acc[i][2] - tmax), p3 = __expf(acc[i][3] - tmax);
            float rsum = p0 + p1 + p2 + p3;
            #pragma unroll
            for (int off = 1; off < 16; off <<= 1)
                rsum += __shfl_xor_sync(0xffffffffu, rsum, off);
            lrun[i] = lrun[i]*corr + rsum;
            #pragma unroll
            for (int j = 0; j < 4; j++) O[i][j] *= corr;
            Ps[(q0+i)*68 + k0+0] = p0; Ps[(q0+i)*68 + k0+1] = p1;
            Ps[(q0+i)*68 + k0+2] = p2; Ps[(q0+i)*68 + k0+3] = p3;
        }
        __syncthreads();
        #pragma unroll 8
        for (int kk = 0; kk < 64; kk++) {
            float a[4];
            #pragma unroll
            for (int i = 0; i < 4; i++) a[i] = Ps[(q0+i)*68 + kk];
            float4 bv = *reinterpret_cast<const float4*>(&Vs[kk*64 + k0]);
            #pragma unroll
            for (int i = 0; i < 4; i++) {
                O[i][0] += a[i]*bv.x; O[i][1] += a[i]*bv.y;
                O[i][2] += a[i]*bv.z; O[i][3] += a[i]*bv.w;
            }
        }
    }
    #pragma unroll
    for (int i = 0; i < 4; i++) {
        float inv = 1.f / lrun[i];
        float4 v = make_float4(O[i][0]*inv, O[i][1]*inv, O[i][2]*inv, O[i][3]*inv);
        *reinterpret_cast<float4*>(
            &g_ao[((size_t)(b*S_ + qt*64 + q0 + i))*DM + h*HD + k0]) = v;
    }
}

// ---------------- host launch with size-based input routing ----------------
extern "C" void kernel_launch(void* const* d_in, const int* in_sizes, int n_in,
                              void* d_out, int out_size) {
    (void)out_size;
    const float *x = 0, *Wq = 0, *Wk = 0, *Wv = 0, *Wo = 0, *M0 = 0;
    const float *ew = 0, *eb = 0, *aw = 0, *ab = 0, *gw = 0, *gb = 0;
    int n1M = 0, n256K = 0, n2K = 0, nB = 0;
    for (int i = 0; i < n_in; i++) {
        const float* p = (const float*)d_in[i];
        switch (in_sizes[i]) {
            case 8388608: x = p; break;
            case  524288: M0 = p; break;
            case 1048576: if (n1M++ == 0) Wq = p; else Wo = p; break;
            case  262144: if (n256K++ == 0) Wk = p; else Wv = p; break;
            case    2048: { if (n2K == 0) ew = p; else if (n2K == 1) aw = p; else gw = p; n2K++; } break;
            case       2: { if (nB == 0) eb = p; else if (nB == 1) ab = p; else gb = p; nB++; } break;
            default: break;
        }
    }
    float* out = (float*)d_out;

    float *pWcat = 0, *pQkv = 0, *pAo = 0;
    cudaGetSymbolAddress((void**)&pWcat, g_Wcat);
    cudaGetSymbolAddress((void**)&pQkv,  g_qkv);
    cudaGetSymbolAddress((void**)&pAo,   g_ao);

    cudaFuncSetAttribute(k_attn, cudaFuncAttributeMaxDynamicSharedMemorySize, 70000);

    k_trig<<<(S_*32 + 255)/256, 256>>>();
    k_prep<<<(int)(((size_t)DM*NCOLS + 255)/256), 256>>>(Wq, Wk, Wv, M0);

    // one fused projection GEMM: qkv = x @ Wcat
    k_sgemm<<<dim3(NCOLS/128, TOK/128), 256>>>(x, pWcat, pQkv, TOK, NCOLS, DM);

    // low-rank memory machinery
    k_chunkstats<<<B_*NC, 256>>>(x, ew, eb, aw, ab);
    k_m0norm<<<2, 256>>>(M0);
    k_m0proj<<<B_*NC, 256>>>();
    k_recur<<<dim3(B_, 2), 256>>>(gw, gb);
    k_dtok<<<dim3(S_/32, B_), 256>>>(x);
    k_epilogue<<<B_*S_, 256>>>();

    // attention + output projection
    k_attn<<<dim3(S_/64, NH, B_), 256, 70000>>>();
    k_sgemm<<<dim3(DM/128, TOK/128), 256>>>(pAo, Wo, out, TOK, DM, DM);
}

// round 12
// speedup vs baseline: 104.0169x; 1.0466x over previous
#include <cuda_runtime.h>
#include <math.h>
#include <stdint.h>

#define B_  4
#define S_  2048
#define DM  1024
#define NH  16
#define NKV 4
#define HD  64
#define KVD 256
#define CH  64
#define NC  32
#define TOK (B_*S_)
#define NCOLS 2048   // Wq(1024)|Wk(256)|Wv(256)|M0[0]^T(256)|M0[1]^T(256)

// ---------------- device scratch (static; no allocation) ----------------
__device__ float g_Wcat[(size_t)DM*NCOLS];
__device__ float g_qkv[(size_t)TOK*NCOLS];
__device__ float g_cmean[B_*NC*DM];
__device__ float g_kmean[B_*NC*DM];
__device__ float g_inorm[TOK];
__device__ float g_eta[B_*2*NC];
__device__ float g_alpha[B_*2*NC];
__device__ float g_mk0[B_*2*NC*KVD];
__device__ float g_mv0[B_*2*NC*KVD];
__device__ float g_m0n2[2];
__device__ float g_U[B_*2*NC*KVD];
__device__ float g_Qret[B_*2*NC];
__device__ float g_Wret[B_*2*NC*NC];
__device__ float g_D[(size_t)TOK*NC];
__device__ float g_q[(size_t)B_*NH*S_*HD];
__device__ float g_k[(size_t)B_*NKV*S_*HD];
__device__ float g_v[(size_t)B_*NKV*S_*HD];
__device__ float g_ao[(size_t)TOK*DM];
__device__ float g_cos[S_*32];
__device__ float g_sin[S_*32];

#define LOG_ROPE_BASE 13.122363377404331

// ---------------- tf32 helpers ----------------
__device__ __forceinline__ float tf32_rnd(float x) {
    uint32_t u;
    asm("cvt.rna.tf32.f32 %0, %1;" : "=r"(u) : "f"(x));
    return __uint_as_float(u);
}

__device__ __forceinline__ void mma_tf32(float c[4], float a0, float a1, float a2, float a3,
                                         float b0, float b1) {
    asm volatile(
        "mma.sync.aligned.m16n8k8.row.col.f32.tf32.tf32.f32 "
        "{%0,%1,%2,%3}, {%4,%5,%6,%7}, {%8,%9}, {%0,%1,%2,%3};"
        : "+f"(c[0]), "+f"(c[1]), "+f"(c[2]), "+f"(c[3])
        : "r"(__float_as_uint(a0)), "r"(__float_as_uint(a1)),
          "r"(__float_as_uint(a2)), "r"(__float_as_uint(a3)),
          "r"(__float_as_uint(b0)), "r"(__float_as_uint(b1)));
}

// ---------------- RoPE trig table ----------------
__global__ void k_trig() {
    int idx = blockIdx.x*256 + threadIdx.x;
    if (idx >= S_*32) return;
    int pos = idx >> 5, fi = idx & 31;
    double f = exp(-(double)fi * (LOG_ROPE_BASE/32.0));
    double ds, dc;
    sincos((double)pos * f, &ds, &dc);
    g_cos[idx] = (float)dc;
    g_sin[idx] = (float)ds;
}

// ---------------- weight concat: [Wq | Wk | Wv | M0_0^T | M0_1^T] ----------
__global__ __launch_bounds__(256) void k_prep(const float* __restrict__ Wq,
                                              const float* __restrict__ Wk,
                                              const float* __restrict__ Wv,
                                              const float* __restrict__ M0) {
    size_t idx = (size_t)blockIdx.x*256 + threadIdx.x;
    if (idx >= (size_t)DM*NCOLS) return;
    int d = (int)(idx / NCOLS), c = (int)(idx % NCOLS);
    float v;
    if (c < 1024)       v = Wq[(size_t)d*1024 + c];
    else if (c < 1280)  v = Wk[(size_t)d*256 + (c-1024)];
    else if (c < 1536)  v = Wv[(size_t)d*256 + (c-1280)];
    else if (c < 1792)  v = M0[(size_t)(c-1536)*DM + d];
    else                v = M0[(size_t)(KVD + (c-1792))*DM + d];
    g_Wcat[idx] = v;
}

// ---------------- tensor-core GEMM (3xTF32): C[M,N] = A[M,K] @ B[K,N] -------
// 128x128x16 block tile, 8 warps (2x4), 64x32 warp tile, m16n8k8 mma.
#define APAD 20
#define BPAD 136
__global__ __launch_bounds__(256) void k_mma(const float* __restrict__ A,
                                             const float* __restrict__ B,
                                             float* __restrict__ C,
                                             int M, int N, int K) {
    __shared__ float AsHi[128*APAD], AsLo[128*APAD];
    __shared__ float BsHi[16*BPAD],  BsLo[16*BPAD];
    int tid = threadIdx.x, wid = tid >> 5, lane = tid & 31;
    int wm = wid >> 2, wn = wid & 3;
    int g = lane >> 2, tg = lane & 3;
    int bm = blockIdx.y * 128, bn = blockIdx.x * 128;

    int arow = tid >> 2, aq = (tid & 3) * 4;       // A stage: 2 iters (rows 0-63, 64-127)
    int brow = tid >> 5, bq = (tid & 31) * 4;      // B stage: 2 iters (rows 0-7, 8-15)

    float c[4][4][4];
    #pragma unroll
    for (int mt = 0; mt < 4; mt++)
        #pragma unroll
        for (int nt = 0; nt < 4; nt++)
            #pragma unroll
            for (int r = 0; r < 4; r++) c[mt][nt][r] = 0.f;

    // initial stage
    float4 rA[2], rB[2];
    rA[0] = *reinterpret_cast<const float4*>(&A[(size_t)(bm+arow)*K + aq]);
    rA[1] = *reinterpret_cast<const float4*>(&A[(size_t)(bm+arow+64)*K + aq]);
    rB[0] = *reinterpret_cast<const float4*>(&B[(size_t)brow*N + bn + bq]);
    rB[1] = *reinterpret_cast<const float4*>(&B[(size_t)(brow+8)*N + bn + bq]);
    #pragma unroll
    for (int it = 0; it < 2; it++) {
        int r = arow + it*64;
        float vv[4] = {rA[it].x, rA[it].y, rA[it].z, rA[it].w};
        #pragma unroll
        for (int j = 0; j < 4; j++) {
            float hi = tf32_rnd(vv[j]);
            AsHi[r*APAD + aq + j] = hi;
            AsLo[r*APAD + aq + j] = tf32_rnd(vv[j] - hi);
        }
        int r2 = brow + it*8;
        float vb[4] = {rB[it].x, rB[it].y, rB[it].z, rB[it].w};
        #pragma unroll
        for (int j = 0; j < 4; j++) {
            float hi = tf32_rnd(vb[j]);
            BsHi[r2*BPAD + bq + j] = hi;
            BsLo[r2*BPAD + bq + j] = tf32_rnd(vb[j] - hi);
        }
    }
    __syncthreads();

    for (int k0 = 0; k0 < K; k0 += 16) {
        // prefetch next tile
        bool more = (k0 + 16) < K;
        if (more) {
            rA[0] = *reinterpret_cast<const float4*>(&A[(size_t)(bm+arow)*K + k0+16 + aq]);
            rA[1] = *reinterpret_cast<const float4*>(&A[(size_t)(bm+arow+64)*K + k0+16 + aq]);
            rB[0] = *reinterpret_cast<const float4*>(&B[(size_t)(k0+16+brow)*N + bn + bq]);
            rB[1] = *reinterpret_cast<const float4*>(&B[(size_t)(k0+16+brow+8)*N + bn + bq]);
        }
        // compute on staged tile
        #pragma unroll
        for (int k8 = 0; k8 < 2; k8++) {
            int kk = k8*8;
            float aHi[4][4], aLo[4][4];
            #pragma unroll
            for (int mt = 0; mt < 4; mt++) {
                int r0 = wm*64 + mt*16 + g;
                aHi[mt][0] = AsHi[r0*APAD + kk+tg];
                aHi[mt][1] = AsHi[(r0+8)*APAD + kk+tg];
                aHi[mt][2] = AsHi[r0*APAD + kk+tg+4];
                aHi[mt][3] = AsHi[(r0+8)*APAD + kk+tg+4];
                aLo[mt][0] = AsLo[r0*APAD + kk+tg];
                aLo[mt][1] = AsLo[(r0+8)*APAD + kk+tg];
                aLo[mt][2] = AsLo[r0*APAD + kk+tg+4];
                aLo[mt][3] = AsLo[(r0+8)*APAD + kk+tg+4];
            }
            float bHi[4][2], bLo[4][2];
            #pragma unroll
            for (int nt = 0; nt < 4; nt++) {
                int col = wn*32 + nt*8 + g;
                bHi[nt][0] = BsHi[(kk+tg)*BPAD + col];
                bHi[nt][1] = BsHi[(kk+tg+4)*BPAD + col];
                bLo[nt][0] = BsLo[(kk+tg)*BPAD + col];
                bLo[nt][1] = BsLo[(kk+tg+4)*BPAD + col];
            }
            #pragma unroll
            for (int mt = 0; mt < 4; mt++)
                #pragma unroll
                for (int nt = 0; nt < 4; nt++) {
                    mma_tf32(c[mt][nt], aHi[mt][0], aHi[mt][1], aHi[mt][2], aHi[mt][3],
                             bHi[nt][0], bHi[nt][1]);
                    mma_tf32(c[mt][nt], aHi[mt][0], aHi[mt][1], aHi[mt][2], aHi[mt][3],
                             bLo[nt][0], bLo[nt][1]);
                    mma_tf32(c[mt][nt], aLo[mt][0], aLo[mt][1], aLo[mt][2], aLo[mt][3],
                             bHi[nt][0], bHi[nt][1]);
                }
        }
        __syncthreads();
        if (more) {
            #pragma unroll
            for (int it = 0; it < 2; it++) {
                int r = arow + it*64;
                float vv[4] = {rA[it].x, rA[it].y, rA[it].z, rA[it].w};
                #pragma unroll
                for (int j = 0; j < 4; j++) {
                    float hi = tf32_rnd(vv[j]);
                    AsHi[r*APAD + aq + j] = hi;
                    AsLo[r*APAD + aq + j] = tf32_rnd(vv[j] - hi);
                }
                int r2 = brow + it*8;
                float vb[4] = {rB[it].x, rB[it].y, rB[it].z, rB[it].w};
                #pragma unroll
                for (int j = 0; j < 4; j++) {
                    float hi = tf32_rnd(vb[j]);
                    BsHi[r2*BPAD + bq + j] = hi;
                    BsLo[r2*BPAD + bq + j] = tf32_rnd(vb[j] - hi);
                }
            }
            __syncthreads();
        }
    }

    // store C
    #pragma unroll
    for (int mt = 0; mt < 4; mt++) {
        int row = bm + wm*64 + mt*16 + g;
        #pragma unroll
        for (int nt = 0; nt < 4; nt++) {
            int col = bn + wn*32 + nt*8 + tg*2;
            *reinterpret_cast<float2*>(&C[(size_t)row*N + col]) =
                make_float2(c[mt][nt][0], c[mt][nt][1]);
            *reinterpret_cast<float2*>(&C[(size_t)(row+8)*N + col]) =
                make_float2(c[mt][nt][2], c[mt][nt][3]);
        }
    }
}

// ---------------- per-chunk stats (cmean, kmean, inorm, eta, alpha) --------
__global__ __launch_bounds__(256) void k_chunkstats(const float* __restrict__ x,
                                                    const float* __restrict__ ew,
                                                    const float* __restrict__ eb,
                                                    const float* __restrict__ aw,
                                                    const float* __restrict__ ab) {
    int b = blockIdx.x >> 5, i = blockIdx.x & 31;
    const float* cx = x + ((size_t)(b*S_) + i*CH) * DM;
    __shared__ float inorm[CH];
    __shared__ float wacc[8][4];
    int tid = threadIdx.x, w = tid >> 5, lane = tid & 31;
    float a0 = 0.f, a1 = 0.f, a2 = 0.f, a3 = 0.f;
    for (int t = w; t < CH; t += 8) {
        const float* row = cx + (size_t)t * DM;
        float sq = 0.f, d0 = 0.f, d1 = 0.f, d2 = 0.f, d3 = 0.f;
        for (int d = lane; d < DM; d += 32) {
            float v = row[d];
            sq += v*v;
            d0 += v*ew[d];    d1 += v*ew[DM+d];
            d2 += v*aw[d];    d3 += v*aw[DM+d];
        }
        #pragma unroll
        for (int off = 16; off; off >>= 1) {
            sq += __shfl_xor_sync(0xffffffffu, sq, off);
            d0 += __shfl_xor_sync(0xffffffffu, d0, off);
            d1 += __shfl_xor_sync(0xffffffffu, d1, off);
            d2 += __shfl_xor_sync(0xffffffffu, d2, off);
            d3 += __shfl_xor_sync(0xffffffffu, d3, off);
        }
        if (lane == 0) {
            float in = 1.f / fmaxf(sqrtf(sq), 1e-5f);
            inorm[t] = in;
            g_inorm[b*S_ + i*CH + t] = in;
            a0 += 1.f/(1.f + expf(-(d0 + eb[0])));
            a1 += 1.f/(1.f + expf(-(d1 + eb[1])));
            a2 += 1.f/(1.f + expf(-(d2 + ab[0])));
            a3 += 1.f/(1.f + expf(-(d3 + ab[1])));
        }
    }
    if (lane == 0) { wacc[w][0]=a0; wacc[w][1]=a1; wacc[w][2]=a2; wacc[w][3]=a3; }
    __syncthreads();
    if (tid == 0) {
        float e0=0.f,e1=0.f,l0=0.f,l1=0.f;
        for (int ww = 0; ww < 8; ww++) { e0+=wacc[ww][0]; e1+=wacc[ww][1]; l0+=wacc[ww][2]; l1+=wacc[ww][3]; }
        g_eta  [(b*2+0)*NC+i] = 0.2f * e0 * (1.f/64.f);
        g_eta  [(b*2+1)*NC+i] = 0.2f * e1 * (1.f/64.f);
        g_alpha[(b*2+0)*NC+i] = 0.5f + 0.5f * l0 * (1.f/64.f);
        g_alpha[(b*2+1)*NC+i] = 0.5f + 0.5f * l1 * (1.f/64.f);
    }
    __syncthreads();
    for (int d = tid; d < DM; d += 256) {
        float sc = 0.f, sk = 0.f;
        for (int t = 0; t < CH; t++) {
            float v = cx[(size_t)t*DM + d];
            sc += v;
            sk += v * inorm[t];
        }
        g_cmean[(b*NC+i)*DM + d] = sc * (1.f/64.f);
        g_kmean[(b*NC+i)*DM + d] = sk * (1.f/64.f);
    }
}

// ---------------- ||M0||^2 ----------------
__global__ __launch_bounds__(256) void k_m0norm(const float* __restrict__ M0) {
    int m = blockIdx.x;
    __shared__ float red[8];
    float s = 0.f;
    const float* p = M0 + (size_t)m * KVD * DM;
    for (int idx = threadIdx.x; idx < KVD*DM; idx += 256) { float v = p[idx]; s += v*v; }
    #pragma unroll
    for (int off = 16; off; off >>= 1) s += __shfl_xor_sync(0xffffffffu, s, off);
    int w = threadIdx.x >> 5, lane = threadIdx.x & 31;
    if (lane == 0) red[w] = s;
    __syncthreads();
    if (threadIdx.x == 0) {
        float t = 0.f;
        for (int ww = 0; ww < 8; ww++) t += red[ww];
        g_m0n2[m] = t;
    }
}

// ---------------- M0@cmean, M0@kmean from qkv columns ----------------
__global__ __launch_bounds__(256) void k_m0proj() {
    int b = blockIdx.x >> 5, i = blockIdx.x & 31;
    int tid = threadIdx.x;
    const float* base = g_qkv + (size_t)(b*S_ + i*CH)*NCOLS;
    const float* inr = g_inorm + b*S_ + i*CH;
    for (int p = tid; p < 512; p += 256) {
        int col = 1536 + p;
        float sc = 0.f, sk = 0.f;
        for (int t = 0; t < CH; t++) {
            float v = base[(size_t)t*NCOLS + col];
            sc += v;
            sk += v * inr[t];
        }
        int m = p >> 8, o = p & 255;
        g_mv0[((b*2+m)*NC+i)*KVD + o] = sc * (1.f/64.f);
        g_mk0[((b*2+m)*NC+i)*KVD + o] = sk * (1.f/64.f);
    }
}

// ---------------- sequential low-rank recurrence (8 blocks, tiny) ----------
__global__ __launch_bounds__(256) void k_recur(const float* __restrict__ gw,
                                               const float* __restrict__ gb) {
    int b = blockIdx.x, m = blockIdx.y;
    __shared__ float kks[NC*NC];
    __shared__ float kcs[NC*NC];
    __shared__ float errs[NC*KVD];
    __shared__ float gates[NC], Wcur[NC];
    __shared__ float red1[8], red2[8], bc[2];
    int tid = threadIdx.x, w = tid >> 5, lane = tid & 31;
    const float* kmb = g_kmean + (size_t)b*NC*DM;
    const float* cmb = g_cmean + (size_t)b*NC*DM;
    for (int p = w; p < 2*NC*NC; p += 8) {
        int pi = (p < NC*NC) ? p : p - NC*NC;
        int i = pi >> 5, j = pi & 31;
        const float* u  = kmb + (size_t)j*DM;
        const float* vv = (p < NC*NC) ? (kmb + (size_t)i*DM) : (cmb + (size_t)i*DM);
        float s = 0.f;
        for (int d = lane; d < DM; d += 32) s += u[d]*vv[d];
        #pragma unroll
        for (int off = 16; off; off >>= 1) s += __shfl_xor_sync(0xffffffffu, s, off);
        if (lane == 0) { if (p < NC*NC) kks[i*NC+j] = s; else kcs[i*NC+j] = s; }
    }
    for (int g = w; g < NC; g += 8) {
        const float* u = kmb + (size_t)g*DM;
        float s = 0.f;
        for (int d = lane; d < DM; d += 32) s += u[d]*gw[m*DM + d];
        #pragma unroll
        for (int off = 16; off; off >>= 1) s += __shfl_xor_sync(0xffffffffu, s, off);
        if (lane == 0) gates[g] = 1.f/(1.f + expf(-(s + gb[m])));
    }
    if (tid < NC) Wcur[tid] = 0.f;
    __syncthreads();

    float Q = 1.f, N2 = g_m0n2[m];
    int bm = b*2 + m;
    int o = tid;
    for (int i = 0; i < NC; i++) {
        float vt = Q * g_mv0[(bm*NC+i)*KVD + o];
        float mk = Q * g_mk0[(bm*NC+i)*KVD + o];
        for (int j = 0; j < i; j++) {
            float we = Wcur[j] * errs[j*KVD + o];
            vt += we * kcs[i*NC+j];
            mk += we * kks[i*NC+j];
        }
        float e = vt - mk;
        errs[i*KVD + o] = e;
        g_U[(bm*NC+i)*KVD + o] = e;
        float p1 = mk*e, p2 = e*e;
        #pragma unroll
        for (int off = 16; off; off >>= 1) {
            p1 += __shfl_xor_sync(0xffffffffu, p1, off);
            p2 += __shfl_xor_sync(0xffffffffu, p2, off);
        }
        if (lane == 0) { red1[w] = p1; red2[w] = p2; }
        __syncthreads();
        if (tid == 0) {
            float s1 = 0.f, s2 = 0.f;
            for (int ww = 0; ww < 8; ww++) { s1 += red1[ww]; s2 += red2[ww]; }
            bc[0] = s1; bc[1] = s2;
        }
        __syncthreads();
        float dot1 = bc[0], errsq = bc[1];
        float gt = gates[i];
        float eta = g_eta[bm*NC+i], al = g_alpha[bm*NC+i];
        float a  = gt*al + 1.f - gt;
        float b0 = gt*eta;
        float m2 = a*a*N2 + 2.f*a*b0*dot1 + b0*b0*errsq*kks[i*NC+i];
        float s  = fminf(30.f/(sqrtf(m2) + 1e-6f), 1.f);
        if (tid < NC) g_Wret[(bm*NC+i)*NC + tid] = (tid < i) ? Wcur[tid] : 0.f;
        if (tid == 0) g_Qret[bm*NC+i] = Q;
        __syncthreads();
        if (tid < NC) { if (tid < i) Wcur[tid] *= s*a; else if (tid == i) Wcur[tid] = s*b0; }
        Q *= s*a;
        N2 = s*s*m2;
        __syncthreads();
    }
}

// ---------------- D[b,t,j] = x_t . kmean_j ----------------
__global__ __launch_bounds__(256) void k_dtok(const float* __restrict__ x) {
    __shared__ float xs[32][128];
    __shared__ float ks[32][129];
    int b = blockIdx.y, t0 = blockIdx.x * 32;
    int tid = threadIdx.x;
    int tl = tid >> 5, j = tid & 31;
    float acc[4] = {0.f, 0.f, 0.f, 0.f};
    for (int d0 = 0; d0 < DM; d0 += 128) {
        #pragma unroll
        for (int it = 0; it < 4; it++) {
            int lin = tid + it*256;
            int r = lin >> 5, q = lin & 31;
            float4 xv = *reinterpret_cast<const float4*>(&x[((size_t)(b*S_) + t0 + r)*DM + d0 + q*4]);
            *reinterpret_cast<float4*>(&xs[r][q*4]) = xv;
            float4 kv = *reinterpret_cast<const float4*>(&g_kmean[((size_t)(b*NC) + r)*DM + d0 + q*4]);
            ks[r][q*4+0] = kv.x; ks[r][q*4+1] = kv.y; ks[r][q*4+2] = kv.z; ks[r][q*4+3] = kv.w;
        }
        __syncthreads();
        #pragma unroll
        for (int tt = 0; tt < 4; tt++) {
            int t = tl + tt*8;
            float s = 0.f;
            #pragma unroll 16
            for (int d = 0; d < 128; d++) s += xs[t][d]*ks[j][d];
            acc[tt] += s;
        }
        __syncthreads();
    }
    #pragma unroll
    for (int tt = 0; tt < 4; tt++)
        g_D[((size_t)(b*S_) + t0 + tl + tt*8)*NC + j] = acc[tt];
}

// ---------------- build q(rope), k(mem+rope), v(mem) ----------------
__global__ __launch_bounds__(256) void k_epilogue() {
    int blk = blockIdx.x;
    int b = blk >> 11, pos = blk & 2047;
    int i = pos >> 6;
    int tid = threadIdx.x;
    __shared__ float wd0[NC], wd1[NC], kbuf[KVD];
    if (tid < 32) {
        float Dv = g_D[((size_t)(b*S_) + pos)*NC + tid];
        wd0[tid] = g_Wret[((b*2+0)*NC+i)*NC + tid] * Dv;
        wd1[tid] = g_Wret[((b*2+1)*NC+i)*NC + tid] * Dv;
    }
    __syncthreads();
    const float* row = g_qkv + (size_t)(b*S_ + pos) * NCOLS;
    float q0 = g_Qret[(b*2+0)*NC+i], q1 = g_Qret[(b*2+1)*NC+i];
    int o = tid;
    float kval = row[1024 + o] + q0 * row[1536 + o];
    float vval = row[1280 + o] + q1 * row[1792 + o];
    const float* U0 = g_U + (size_t)(b*2+0)*NC*KVD;
    const float* U1 = g_U + (size_t)(b*2+1)*NC*KVD;
    #pragma unroll 8
    for (int j = 0; j < NC; j++) {
        kval += wd0[j] * U0[j*KVD + o];
        vval += wd1[j] * U1[j*KVD + o];
    }
    kbuf[o] = kval;
    __syncthreads();
    int d = o & 63, kv = o >> 6;
    float cs = g_cos[pos*32 + (d & 31)], sn = g_sin[pos*32 + (d & 31)];
    float rot = (d < 32) ? -kbuf[kv*64 + d + 32] : kbuf[kv*64 + d - 32];
    size_t kidx = (((size_t)(b*NKV) + kv)*S_ + pos)*HD + d;
    g_k[kidx] = kval*cs + rot*sn;
    g_v[kidx] = vval;
    for (int oq = tid; oq < DM; oq += 256) {
        float qv = row[oq];
        int dd = oq & 63, h = oq >> 6;
        float part = row[h*64 + ((dd < 32) ? dd + 32 : dd - 32)];
        float rq = (dd < 32) ? -part : part;
        float c2 = g_cos[pos*32 + (dd & 31)], s2 = g_sin[pos*32 + (dd & 31)];
        g_q[(((size_t)(b*NH) + h)*S_ + pos)*HD + dd] = qv*c2 + rq*s2;
    }
}

// ---------------- causal flash attention, GEMM-style 4x4 register tiling ----
__global__ __launch_bounds__(256) void k_attn() {
    extern __shared__ float sm[];
    float* Qs = sm;              // 64*64
    float* Kt = Qs + 4096;       // 64*68 (transposed)
    float* Vs = Kt + 64*68;      // 64*64
    float* Ps = Vs + 4096;       // 64*68
    int qt = blockIdx.x, h = blockIdx.y, b = blockIdx.z;
    int tid = threadIdx.x;
    int tx = tid & 15, ty = tid >> 4;
    int q0 = ty*4, k0 = tx*4;

    const float* Qbase = g_q + (((size_t)b*NH + h)*S_ + (size_t)qt*64)*HD;
    #pragma unroll
    for (int it = 0; it < 4; it++) {
        int lin = tid + it*256;
        int r = lin >> 4, c = (lin & 15)*4;
        float4 v = *reinterpret_cast<const float4*>(&Qbase[(size_t)r*HD + c]);
        Qs[r*64+c+0] = v.x*0.125f; Qs[r*64+c+1] = v.y*0.125f;
        Qs[r*64+c+2] = v.z*0.125f; Qs[r*64+c+3] = v.w*0.125f;
    }

    float O[4][4];
    float mrun[4], lrun[4];
    #pragma unroll
    for (int i = 0; i < 4; i++) {
        mrun[i] = -1e30f; lrun[i] = 0.f;
        #pragma unroll
        for (int j = 0; j < 4; j++) O[i][j] = 0.f;
    }

    int kvh = h >> 2;
    const float* Kbase = g_k + ((size_t)b*NKV + kvh)*S_*HD;
    const float* Vbase = g_v + ((size_t)b*NKV + kvh)*S_*HD;

    for (int kt = 0; kt <= qt; kt++) {
        __syncthreads();
        {
            int r = tid >> 2, q = tid & 3;
            const float* krow = &Kbase[(size_t)(kt*64 + r)*HD + q*16];
            #pragma unroll
            for (int c4 = 0; c4 < 4; c4++) {
                float4 v = *reinterpret_cast<const float4*>(&krow[c4*4]);
                int d = q*16 + c4*4;
                Kt[(d+0)*68 + r] = v.x; Kt[(d+1)*68 + r] = v.y;
                Kt[(d+2)*68 + r] = v.z; Kt[(d+3)*68 + r] = v.w;
            }
        }
        #pragma unroll
        for (int it = 0; it < 4; it++) {
            int lin = tid + it*256;
            int r = lin >> 4, c = (lin & 15)*4;
            *reinterpret_cast<float4*>(&Vs[r*64+c]) =
                *reinterpret_cast<const float4*>(&Vbase[(size_t)(kt*64 + r)*HD + c]);
        }
        __syncthreads();

        float acc[4][4];
        #pragma unroll
        for (int i = 0; i < 4; i++)
            #pragma unroll
            for (int j = 0; j < 4; j++) acc[i][j] = 0.f;
        #pragma unroll 8
        for (int d = 0; d < 64; d++) {
            float a[4];
            #pragma unroll
            for (int i = 0; i < 4; i++) a[i] = Qs[(q0+i)*64 + d];
            float4 bv = *reinterpret_cast<const float4*>(&Kt[d*68 + k0]);
            #pragma unroll
            for (int i = 0; i < 4; i++) {
                acc[i][0] += a[i]*bv.x; acc[i][1] += a[i]*bv.y;
                acc[i][2] += a[i]*bv.z; acc[i][3] += a[i]*bv.w;
            }
        }
        if (kt == qt) {
            #pragma unroll
            for (int i = 0; i < 4; i++)
                #pragma unroll
                for (int j = 0; j < 4; j++)
                    if (k0 + j > q0 + i) acc[i][j] = -1e30f;
        }
        #pragma unroll
        for (int i = 0; i < 4; i++) {
            float rmax = fmaxf(fmaxf(acc[i][0], acc[i][1]), fmaxf(acc[i][2], acc[i][3]));
            #pragma unroll
            for (int off = 1; off < 16; off <<= 1)
                rmax = fmaxf(rmax, __shfl_xor_sync(0xffffffffu, rmax, off));
            float tmax = fmaxf(mrun[i], rmax);
            float corr = __expf(mrun[i] - tmax);
            mrun[i] = tmax;
            float p0 = __expf(acc[i][0] - tmax), p1 = __expf(acc[i][1] - tmax);
            float p2 = __expf(acc[i][2] - tmax), p3 = __expf(acc[i][3] - tmax);
            float rsum = p0 + p1 + p2 + p3;
            #pragma unroll
            for (int off = 1; off < 16; off <<= 1)
                rsum += __shfl_xor_sync(0xffffffffu, rsum, off);
            lrun[i] = lrun[i]*corr + rsum;
            #pragma unroll
            for (int j = 0; j < 4; j++) O[i][j] *= corr;
            Ps[(q0+i)*68 + k0+0] = p0; Ps[(q0+i)*68 + k0+1] = p1;
            Ps[(q0+i)*68 + k0+2] = p2; Ps[(q0+i)*68 + k0+3] = p3;
        }
        __syncthreads();
        #pragma unroll 8
        for (int kk = 0; kk < 64; kk++) {
            float a[4];
            #pragma unroll
            for (int i = 0; i < 4; i++) a[i] = Ps[(q0+i)*68 + kk];
            float4 bv = *reinterpret_cast<const float4*>(&Vs[kk*64 + k0]);
            #pragma unroll
            for (int i = 0; i < 4; i++) {
                O[i][0] += a[i]*bv.x; O[i][1] += a[i]*bv.y;
                O[i][2] += a[i]*bv.z; O[i][3] += a[i]*bv.w;
            }
        }
    }
    #pragma unroll
    for (int i = 0; i < 4; i++) {
        float inv = 1.f / lrun[i];
        float4 v = make_float4(O[i][0]*inv, O[i][1]*inv, O[i][2]*inv, O[i][3]*inv);
        *reinterpret_cast<float4*>(
            &g_ao[((size_t)(b*S_ + qt*64 + q0 + i))*DM + h*HD + k0]) = v;
    }
}

// ---------------- host launch with size-based input routing ----------------
extern "C" void kernel_launch(void* const* d_in, const int* in_sizes, int n_in,
                              void* d_out, int out_size) {
    (void)out_size;
    const float *x = 0, *Wq = 0, *Wk = 0, *Wv = 0, *Wo = 0, *M0 = 0;
    const float *ew = 0, *eb = 0, *aw = 0, *ab = 0, *gw = 0, *gb = 0;
    int n1M = 0, n256K = 0, n2K = 0, nB = 0;
    for (int i = 0; i < n_in; i++) {
        const float* p = (const float*)d_in[i];
        switch (in_sizes[i]) {
            case 8388608: x = p; break;
            case  524288: M0 = p; break;
            case 1048576: if (n1M++ == 0) Wq = p; else Wo = p; break;
            case  262144: if (n256K++ == 0) Wk = p; else Wv = p; break;
            case    2048: { if (n2K == 0) ew = p; else if (n2K == 1) aw = p; else gw = p; n2K++; } break;
            case       2: { if (nB == 0) eb = p; else if (nB == 1) ab = p; else gb = p; nB++; } break;
            default: break;
        }
    }
    float* out = (float*)d_out;

    float *pWcat = 0, *pQkv = 0, *pAo = 0;
    cudaGetSymbolAddress((void**)&pWcat, g_Wcat);
    cudaGetSymbolAddress((void**)&pQkv,  g_qkv);
    cudaGetSymbolAddress((void**)&pAo,   g_ao);

    cudaFuncSetAttribute(k_attn, cudaFuncAttributeMaxDynamicSharedMemorySize, 70000);

    k_trig<<<(S_*32 + 255)/256, 256>>>();
    k_prep<<<(int)(((size_t)DM*NCOLS + 255)/256), 256>>>(Wq, Wk, Wv, M0);

    // fused projection GEMM (tensor cores): qkv = x @ Wcat
    k_mma<<<dim3(NCOLS/128, TOK/128), 256>>>(x, pWcat, pQkv, TOK, NCOLS, DM);

    // low-rank memory machinery
    k_chunkstats<<<B_*NC, 256>>>(x, ew, eb, aw, ab);
    k_m0norm<<<2, 256>>>(M0);
    k_m0proj<<<B_*NC, 256>>>();
    k_recur<<<dim3(B_, 2), 256>>>(gw, gb);
    k_dtok<<<dim3(S_/32, B_), 256>>>(x);
    k_epilogue<<<B_*S_, 256>>>();

    // attention + output projection (tensor cores)
    k_attn<<<dim3(S_/64, NH, B_), 256, 70000>>>();
    k_mma<<<dim3(DM/128, TOK/128), 256>>>(pAo, Wo, out, TOK, DM, DM);
}

// round 13
// speedup vs baseline: 109.8388x; 1.0560x over previous
#include <cuda_runtime.h>
#include <cuda_bf16.h>
#include <math.h>
#include <stdint.h>

#define B_  4
#define S_  2048
#define DM  1024
#define NH  16
#define NKV 4
#define HD  64
#define KVD 256
#define CH  64
#define NC  32
#define TOK (B_*S_)
#define NCOLS 2048   // Wq(1024)|Wk(256)|Wv(256)|M0[0]^T(256)|M0[1]^T(256)

// ---------------- device scratch (static; no allocation) ----------------
__device__ float g_Wcat[(size_t)DM*NCOLS];
__device__ float g_qkv[(size_t)TOK*NCOLS];
__device__ float g_cmean[B_*NC*DM];
__device__ float g_kmean[B_*NC*DM];
__device__ float g_inorm[TOK];
__device__ float g_eta[B_*2*NC];
__device__ float g_alpha[B_*2*NC];
__device__ float g_mk0[B_*2*NC*KVD];
__device__ float g_mv0[B_*2*NC*KVD];
__device__ float g_m0n2[2];
__device__ float g_U[B_*2*NC*KVD];
__device__ float g_Qret[B_*2*NC];
__device__ float g_Wret[B_*2*NC*NC];
__device__ float g_D[(size_t)TOK*NC];
__device__ float g_q[(size_t)B_*NH*S_*HD];
__device__ float g_k[(size_t)B_*NKV*S_*HD];
__device__ float g_v[(size_t)B_*NKV*S_*HD];
__device__ float g_ao[(size_t)TOK*DM];
__device__ float g_cos[S_*32];
__device__ float g_sin[S_*32];

#define LOG_ROPE_BASE 13.122363377404331

// ---------------- bf16 helpers ----------------
__device__ __forceinline__ uint32_t pack_bf16(float a, float b) {
    __nv_bfloat16 ha = __float2bfloat16_rn(a);
    __nv_bfloat16 hb = __float2bfloat16_rn(b);
    uint16_t ua = __bfloat16_as_ushort(ha);
    uint16_t ub = __bfloat16_as_ushort(hb);
    return ((uint32_t)ub << 16) | ua;
}
__device__ __forceinline__ float bf16_hi(float x) {
    return __bfloat162float(__float2bfloat16_rn(x));
}

__device__ __forceinline__ void mma_bf16(float c[4], uint32_t a0, uint32_t a1,
                                         uint32_t a2, uint32_t a3,
                                         uint32_t b0, uint32_t b1) {
    asm volatile(
        "mma.sync.aligned.m16n8k16.row.col.f32.bf16.bf16.f32 "
        "{%0,%1,%2,%3}, {%4,%5,%6,%7}, {%8,%9}, {%0,%1,%2,%3};"
        : "+f"(c[0]), "+f"(c[1]), "+f"(c[2]), "+f"(c[3])
        : "r"(a0), "r"(a1), "r"(a2), "r"(a3), "r"(b0), "r"(b1));
}

// ---------------- RoPE trig table ----------------
__global__ void k_trig() {
    int idx = blockIdx.x*256 + threadIdx.x;
    if (idx >= S_*32) return;
    int pos = idx >> 5, fi = idx & 31;
    double f = exp(-(double)fi * (LOG_ROPE_BASE/32.0));
    double ds, dc;
    sincos((double)pos * f, &ds, &dc);
    g_cos[idx] = (float)dc;
    g_sin[idx] = (float)ds;
}

// ---------------- weight concat ----------------
__global__ __launch_bounds__(256) void k_prep(const float* __restrict__ Wq,
                                              const float* __restrict__ Wk,
                                              const float* __restrict__ Wv,
                                              const float* __restrict__ M0) {
    size_t idx = (size_t)blockIdx.x*256 + threadIdx.x;
    if (idx >= (size_t)DM*NCOLS) return;
    int d = (int)(idx / NCOLS), c = (int)(idx % NCOLS);
    float v;
    if (c < 1024)       v = Wq[(size_t)d*1024 + c];
    else if (c < 1280)  v = Wk[(size_t)d*256 + (c-1024)];
    else if (c < 1536)  v = Wv[(size_t)d*256 + (c-1280)];
    else if (c < 1792)  v = M0[(size_t)(c-1536)*DM + d];
    else                v = M0[(size_t)(KVD + (c-1792))*DM + d];
    g_Wcat[idx] = v;
}

// ---------------- tensor-core GEMM (3x bf16 m16n8k16): C = A @ B ------------
// 128x128 block tile, K-step 32, 8 warps (2x4), 64x32 warp tile.
#define PAD 18   // uint32 words per row (16 k-pairs + 2 pad)
__global__ __launch_bounds__(256) void k_mma(const float* __restrict__ A,
                                             const float* __restrict__ B,
                                             float* __restrict__ C,
                                             int M, int N, int K) {
    __shared__ uint32_t AsHi[128*PAD], AsLo[128*PAD];
    __shared__ uint32_t BtHi[128*PAD], BtLo[128*PAD];
    int tid = threadIdx.x, wid = tid >> 5, lane = tid & 31;
    int wm = wid >> 2, wn = wid & 3;
    int g = lane >> 2, tg = lane & 3;
    int bm = blockIdx.y * 128, bn = blockIdx.x * 128;

    // A staging map: row ra = tid>>2 (+64), col group cq = (tid&3)*8 (fp32 cols)
    int ra = tid >> 2, cq = (tid & 3) * 8;
    // B staging map: k-row kb = tid>>3, col group nb = (tid&7)*16
    int kb = tid >> 3, nb = (tid & 7) * 16;

    float c[4][4][4];
    #pragma unroll
    for (int mt = 0; mt < 4; mt++)
        #pragma unroll
        for (int nt = 0; nt < 4; nt++)
            #pragma unroll
            for (int r = 0; r < 4; r++) c[mt][nt][r] = 0.f;

    float4 rA[2][2], rB[4];
    // initial global load
    #pragma unroll
    for (int p = 0; p < 2; p++)
        #pragma unroll
        for (int j = 0; j < 2; j++)
            rA[p][j] = *reinterpret_cast<const float4*>(
                &A[(size_t)(bm + ra + p*64)*K + cq + j*4]);
    #pragma unroll
    for (int j = 0; j < 4; j++)
        rB[j] = *reinterpret_cast<const float4*>(&B[(size_t)kb*N + bn + nb + j*4]);

    __nv_bfloat16* bHiH = reinterpret_cast<__nv_bfloat16*>(BtHi);
    __nv_bfloat16* bLoH = reinterpret_cast<__nv_bfloat16*>(BtLo);

    // stage lambda (manual)
    auto stage = [&]() {
        #pragma unroll
        for (int p = 0; p < 2; p++) {
            int row = ra + p*64;
            float f[8] = {rA[p][0].x, rA[p][0].y, rA[p][0].z, rA[p][0].w,
                          rA[p][1].x, rA[p][1].y, rA[p][1].z, rA[p][1].w};
            #pragma unroll
            for (int w = 0; w < 4; w++) {
                float h0 = bf16_hi(f[2*w]), h1 = bf16_hi(f[2*w+1]);
                AsHi[row*PAD + (tid&3)*4 + w] = pack_bf16(h0, h1);
                AsLo[row*PAD + (tid&3)*4 + w] = pack_bf16(f[2*w]-h0, f[2*w+1]-h1);
            }
        }
        float fb[16] = {rB[0].x, rB[0].y, rB[0].z, rB[0].w,
                        rB[1].x, rB[1].y, rB[1].z, rB[1].w,
                        rB[2].x, rB[2].y, rB[2].z, rB[2].w,
                        rB[3].x, rB[3].y, rB[3].z, rB[3].w};
        #pragma unroll
        for (int j = 0; j < 16; j++) {
            int col = nb + j;
            float h = bf16_hi(fb[j]);
            bHiH[col*(2*PAD) + kb] = __float2bfloat16_rn(h);
            bLoH[col*(2*PAD) + kb] = __float2bfloat16_rn(fb[j] - h);
        }
    };
    stage();
    __syncthreads();

    for (int k0 = 0; k0 < K; k0 += 32) {
        bool more = (k0 + 32) < K;
        if (more) {
            #pragma unroll
            for (int p = 0; p < 2; p++)
                #pragma unroll
                for (int j = 0; j < 2; j++)
                    rA[p][j] = *reinterpret_cast<const float4*>(
                        &A[(size_t)(bm + ra + p*64)*K + k0 + 32 + cq + j*4]);
            #pragma unroll
            for (int j = 0; j < 4; j++)
                rB[j] = *reinterpret_cast<const float4*>(
                    &B[(size_t)(k0 + 32 + kb)*N + bn + nb + j*4]);
        }
        #pragma unroll
        for (int s = 0; s < 2; s++) {
            int p0 = s*8;
            uint32_t aHi[4][4], aLo[4][4];
            #pragma unroll
            for (int mt = 0; mt < 4; mt++) {
                int r0 = wm*64 + mt*16 + g;
                aHi[mt][0] = AsHi[r0*PAD + p0+tg];
                aHi[mt][1] = AsHi[(r0+8)*PAD + p0+tg];
                aHi[mt][2] = AsHi[r0*PAD + p0+tg+4];
                aHi[mt][3] = AsHi[(r0+8)*PAD + p0+tg+4];
                aLo[mt][0] = AsLo[r0*PAD + p0+tg];
                aLo[mt][1] = AsLo[(r0+8)*PAD + p0+tg];
                aLo[mt][2] = AsLo[r0*PAD + p0+tg+4];
                aLo[mt][3] = AsLo[(r0+8)*PAD + p0+tg+4];
            }
            uint32_t bHi[4][2], bLo[4][2];
            #pragma unroll
            for (int nt = 0; nt < 4; nt++) {
                int col = wn*32 + nt*8 + g;
                bHi[nt][0] = BtHi[col*PAD + p0+tg];
                bHi[nt][1] = BtHi[col*PAD + p0+tg+4];
                bLo[nt][0] = BtLo[col*PAD + p0+tg];
                bLo[nt][1] = BtLo[col*PAD + p0+tg+4];
            }
            #pragma unroll
            for (int mt = 0; mt < 4; mt++)
                #pragma unroll
                for (int nt = 0; nt < 4; nt++) {
                    mma_bf16(c[mt][nt], aHi[mt][0], aHi[mt][1], aHi[mt][2], aHi[mt][3],
                             bHi[nt][0], bHi[nt][1]);
                    mma_bf16(c[mt][nt], aHi[mt][0], aHi[mt][1], aHi[mt][2], aHi[mt][3],
                             bLo[nt][0], bLo[nt][1]);
                    mma_bf16(c[mt][nt], aLo[mt][0], aLo[mt][1], aLo[mt][2], aLo[mt][3],
                             bHi[nt][0], bHi[nt][1]);
                }
        }
        __syncthreads();
        if (more) {
            stage();
            __syncthreads();
        }
    }

    #pragma unroll
    for (int mt = 0; mt < 4; mt++) {
        int row = bm + wm*64 + mt*16 + g;
        #pragma unroll
        for (int nt = 0; nt < 4; nt++) {
            int col = bn + wn*32 + nt*8 + tg*2;
            *reinterpret_cast<float2*>(&C[(size_t)row*N + col]) =
                make_float2(c[mt][nt][0], c[mt][nt][1]);
            *reinterpret_cast<float2*>(&C[(size_t)(row+8)*N + col]) =
                make_float2(c[mt][nt][2], c[mt][nt][3]);
        }
    }
}

// ---------------- per-chunk stats (512 threads) ----------------
__global__ __launch_bounds__(512) void k_chunkstats(const float* __restrict__ x,
                                                    const float* __restrict__ ew,
                                                    const float* __restrict__ eb,
                                                    const float* __restrict__ aw,
                                                    const float* __restrict__ ab) {
    int b = blockIdx.x >> 5, i = blockIdx.x & 31;
    const float* cx = x + ((size_t)(b*S_) + i*CH) * DM;
    __shared__ float inorm[CH];
    __shared__ float wacc[16][4];
    int tid = threadIdx.x, w = tid >> 5, lane = tid & 31;
    float a0 = 0.f, a1 = 0.f, a2 = 0.f, a3 = 0.f;
    for (int t = w; t < CH; t += 16) {
        const float* row = cx + (size_t)t * DM;
        float sq = 0.f, d0 = 0.f, d1 = 0.f, d2 = 0.f, d3 = 0.f;
        for (int d = lane; d < DM; d += 32) {
            float v = row[d];
            sq += v*v;
            d0 += v*ew[d];    d1 += v*ew[DM+d];
            d2 += v*aw[d];    d3 += v*aw[DM+d];
        }
        #pragma unroll
        for (int off = 16; off; off >>= 1) {
            sq += __shfl_xor_sync(0xffffffffu, sq, off);
            d0 += __shfl_xor_sync(0xffffffffu, d0, off);
            d1 += __shfl_xor_sync(0xffffffffu, d1, off);
            d2 += __shfl_xor_sync(0xffffffffu, d2, off);
            d3 += __shfl_xor_sync(0xffffffffu, d3, off);
        }
        if (lane == 0) {
            float in = 1.f / fmaxf(sqrtf(sq), 1e-5f);
            inorm[t] = in;
            g_inorm[b*S_ + i*CH + t] = in;
            a0 += 1.f/(1.f + expf(-(d0 + eb[0])));
            a1 += 1.f/(1.f + expf(-(d1 + eb[1])));
            a2 += 1.f/(1.f + expf(-(d2 + ab[0])));
            a3 += 1.f/(1.f + expf(-(d3 + ab[1])));
        }
    }
    if (lane == 0) { wacc[w][0]=a0; wacc[w][1]=a1; wacc[w][2]=a2; wacc[w][3]=a3; }
    __syncthreads();
    if (tid == 0) {
        float e0=0.f,e1=0.f,l0=0.f,l1=0.f;
        for (int ww = 0; ww < 16; ww++) { e0+=wacc[ww][0]; e1+=wacc[ww][1]; l0+=wacc[ww][2]; l1+=wacc[ww][3]; }
        g_eta  [(b*2+0)*NC+i] = 0.2f * e0 * (1.f/64.f);
        g_eta  [(b*2+1)*NC+i] = 0.2f * e1 * (1.f/64.f);
        g_alpha[(b*2+0)*NC+i] = 0.5f + 0.5f * l0 * (1.f/64.f);
        g_alpha[(b*2+1)*NC+i] = 0.5f + 0.5f * l1 * (1.f/64.f);
    }
    __syncthreads();
    for (int d = tid; d < DM; d += 512) {
        float sc = 0.f, sk = 0.f;
        for (int t = 0; t < CH; t++) {
            float v = cx[(size_t)t*DM + d];
            sc += v;
            sk += v * inorm[t];
        }
        g_cmean[(b*NC+i)*DM + d] = sc * (1.f/64.f);
        g_kmean[(b*NC+i)*DM + d] = sk * (1.f/64.f);
    }
}

// ---------------- ||M0||^2 ----------------
__global__ __launch_bounds__(256) void k_m0norm(const float* __restrict__ M0) {
    int m = blockIdx.x;
    __shared__ float red[8];
    float s = 0.f;
    const float* p = M0 + (size_t)m * KVD * DM;
    for (int idx = threadIdx.x; idx < KVD*DM; idx += 256) { float v = p[idx]; s += v*v; }
    #pragma unroll
    for (int off = 16; off; off >>= 1) s += __shfl_xor_sync(0xffffffffu, s, off);
    int w = threadIdx.x >> 5, lane = threadIdx.x & 31;
    if (lane == 0) red[w] = s;
    __syncthreads();
    if (threadIdx.x == 0) {
        float t = 0.f;
        for (int ww = 0; ww < 8; ww++) t += red[ww];
        g_m0n2[m] = t;
    }
}

// ---------------- M0@cmean, M0@kmean from qkv columns ----------------
__global__ __launch_bounds__(256) void k_m0proj() {
    int b = blockIdx.x >> 5, i = blockIdx.x & 31;
    int tid = threadIdx.x;
    const float* base = g_qkv + (size_t)(b*S_ + i*CH)*NCOLS;
    const float* inr = g_inorm + b*S_ + i*CH;
    for (int p = tid; p < 512; p += 256) {
        int col = 1536 + p;
        float sc = 0.f, sk = 0.f;
        for (int t = 0; t < CH; t++) {
            float v = base[(size_t)t*NCOLS + col];
            sc += v;
            sk += v * inr[t];
        }
        int m = p >> 8, o = p & 255;
        g_mv0[((b*2+m)*NC+i)*KVD + o] = sc * (1.f/64.f);
        g_mk0[((b*2+m)*NC+i)*KVD + o] = sk * (1.f/64.f);
    }
}

// ---------------- sequential low-rank recurrence ----------------
__global__ __launch_bounds__(256) void k_recur(const float* __restrict__ gw,
                                               const float* __restrict__ gb) {
    int b = blockIdx.x, m = blockIdx.y;
    __shared__ float kks[NC*NC];
    __shared__ float kcs[NC*NC];
    __shared__ float errs[NC*KVD];
    __shared__ float gates[NC], Wcur[NC];
    __shared__ float red1[8], red2[8], bc[2];
    int tid = threadIdx.x, w = tid >> 5, lane = tid & 31;
    const float* kmb = g_kmean + (size_t)b*NC*DM;
    const float* cmb = g_cmean + (size_t)b*NC*DM;
    for (int p = w; p < 2*NC*NC; p += 8) {
        int pi = (p < NC*NC) ? p : p - NC*NC;
        int i = pi >> 5, j = pi & 31;
        const float* u  = kmb + (size_t)j*DM;
        const float* vv = (p < NC*NC) ? (kmb + (size_t)i*DM) : (cmb + (size_t)i*DM);
        float s = 0.f;
        for (int d = lane; d < DM; d += 32) s += u[d]*vv[d];
        #pragma unroll
        for (int off = 16; off; off >>= 1) s += __shfl_xor_sync(0xffffffffu, s, off);
        if (lane == 0) { if (p < NC*NC) kks[i*NC+j] = s; else kcs[i*NC+j] = s; }
    }
    for (int g = w; g < NC; g += 8) {
        const float* u = kmb + (size_t)g*DM;
        float s = 0.f;
        for (int d = lane; d < DM; d += 32) s += u[d]*gw[m*DM + d];
        #pragma unroll
        for (int off = 16; off; off >>= 1) s += __shfl_xor_sync(0xffffffffu, s, off);
        if (lane == 0) gates[g] = 1.f/(1.f + expf(-(s + gb[m])));
    }
    if (tid < NC) Wcur[tid] = 0.f;
    __syncthreads();

    float Q = 1.f, N2 = g_m0n2[m];
    int bm = b*2 + m;
    int o = tid;
    for (int i = 0; i < NC; i++) {
        float vt = Q * g_mv0[(bm*NC+i)*KVD + o];
        float mk = Q * g_mk0[(bm*NC+i)*KVD + o];
        for (int j = 0; j < i; j++) {
            float we = Wcur[j] * errs[j*KVD + o];
            vt += we * kcs[i*NC+j];
            mk += we * kks[i*NC+j];
        }
        float e = vt - mk;
        errs[i*KVD + o] = e;
        g_U[(bm*NC+i)*KVD + o] = e;
        float p1 = mk*e, p2 = e*e;
        #pragma unroll
        for (int off = 16; off; off >>= 1) {
            p1 += __shfl_xor_sync(0xffffffffu, p1, off);
            p2 += __shfl_xor_sync(0xffffffffu, p2, off);
        }
        if (lane == 0) { red1[w] = p1; red2[w] = p2; }
        __syncthreads();
        if (tid == 0) {
            float s1 = 0.f, s2 = 0.f;
            for (int ww = 0; ww < 8; ww++) { s1 += red1[ww]; s2 += red2[ww]; }
            bc[0] = s1; bc[1] = s2;
        }
        __syncthreads();
        float dot1 = bc[0], errsq = bc[1];
        float gt = gates[i];
        float eta = g_eta[bm*NC+i], al = g_alpha[bm*NC+i];
        float a  = gt*al + 1.f - gt;
        float b0 = gt*eta;
        float m2 = a*a*N2 + 2.f*a*b0*dot1 + b0*b0*errsq*kks[i*NC+i];
        float s  = fminf(30.f/(sqrtf(m2) + 1e-6f), 1.f);
        if (tid < NC) g_Wret[(bm*NC+i)*NC + tid] = (tid < i) ? Wcur[tid] : 0.f;
        if (tid == 0) g_Qret[bm*NC+i] = Q;
        __syncthreads();
        if (tid < NC) { if (tid < i) Wcur[tid] *= s*a; else if (tid == i) Wcur[tid] = s*b0; }
        Q *= s*a;
        N2 = s*s*m2;
        __syncthreads();
    }
}

// ---------------- D[b,t,j] = x_t . kmean_j ----------------
__global__ __launch_bounds__(256) void k_dtok(const float* __restrict__ x) {
    __shared__ float xs[32][128];
    __shared__ float ks[32][129];
    int b = blockIdx.y, t0 = blockIdx.x * 32;
    int tid = threadIdx.x;
    int tl = tid >> 5, j = tid & 31;
    float acc[4] = {0.f, 0.f, 0.f, 0.f};
    for (int d0 = 0; d0 < DM; d0 += 128) {
        #pragma unroll
        for (int it = 0; it < 4; it++) {
            int lin = tid + it*256;
            int r = lin >> 5, q = lin & 31;
            float4 xv = *reinterpret_cast<const float4*>(&x[((size_t)(b*S_) + t0 + r)*DM + d0 + q*4]);
            *reinterpret_cast<float4*>(&xs[r][q*4]) = xv;
            float4 kv = *reinterpret_cast<const float4*>(&g_kmean[((size_t)(b*NC) + r)*DM + d0 + q*4]);
            ks[r][q*4+0] = kv.x; ks[r][q*4+1] = kv.y; ks[r][q*4+2] = kv.z; ks[r][q*4+3] = kv.w;
        }
        __syncthreads();
        #pragma unroll
        for (int tt = 0; tt < 4; tt++) {
            int t = tl + tt*8;
            float s = 0.f;
            #pragma unroll 16
            for (int d = 0; d < 128; d++) s += xs[t][d]*ks[j][d];
            acc[tt] += s;
        }
        __syncthreads();
    }
    #pragma unroll
    for (int tt = 0; tt < 4; tt++)
        g_D[((size_t)(b*S_) + t0 + tl + tt*8)*NC + j] = acc[tt];
}

// ---------------- build q(rope), k(mem+rope), v(mem) ----------------
__global__ __launch_bounds__(256) void k_epilogue() {
    int blk = blockIdx.x;
    int b = blk >> 11, pos = blk & 2047;
    int i = pos >> 6;
    int tid = threadIdx.x;
    __shared__ float wd0[NC], wd1[NC], kbuf[KVD];
    if (tid < 32) {
        float Dv = g_D[((size_t)(b*S_) + pos)*NC + tid];
        wd0[tid] = g_Wret[((b*2+0)*NC+i)*NC + tid] * Dv;
        wd1[tid] = g_Wret[((b*2+1)*NC+i)*NC + tid] * Dv;
    }
    __syncthreads();
    const float* row = g_qkv + (size_t)(b*S_ + pos) * NCOLS;
    float q0 = g_Qret[(b*2+0)*NC+i], q1 = g_Qret[(b*2+1)*NC+i];
    int o = tid;
    float kval = row[1024 + o] + q0 * row[1536 + o];
    float vval = row[1280 + o] + q1 * row[1792 + o];
    const float* U0 = g_U + (size_t)(b*2+0)*NC*KVD;
    const float* U1 = g_U + (size_t)(b*2+1)*NC*KVD;
    #pragma unroll 8
    for (int j = 0; j < NC; j++) {
        kval += wd0[j] * U0[j*KVD + o];
        vval += wd1[j] * U1[j*KVD + o];
    }
    kbuf[o] = kval;
    __syncthreads();
    int d = o & 63, kv = o >> 6;
    float cs = g_cos[pos*32 + (d & 31)], sn = g_sin[pos*32 + (d & 31)];
    float rot = (d < 32) ? -kbuf[kv*64 + d + 32] : kbuf[kv*64 + d - 32];
    size_t kidx = (((size_t)(b*NKV) + kv)*S_ + pos)*HD + d;
    g_k[kidx] = kval*cs + rot*sn;
    g_v[kidx] = vval;
    for (int oq = tid; oq < DM; oq += 256) {
        float qv = row[oq];
        int dd = oq & 63, h = oq >> 6;
        float part = row[h*64 + ((dd < 32) ? dd + 32 : dd - 32)];
        float rq = (dd < 32) ? -part : part;
        float c2 = g_cos[pos*32 + (dd & 31)], s2 = g_sin[pos*32 + (dd & 31)];
        g_q[(((size_t)(b*NH) + h)*S_ + pos)*HD + dd] = qv*c2 + rq*s2;
    }
}

// ---------------- causal flash attention, GEMM-style 4x4 register tiling ----
__global__ __launch_bounds__(256) void k_attn() {
    extern __shared__ float sm[];
    float* Qs = sm;              // 64*64
    float* Kt = Qs + 4096;       // 64*68 (transposed)
    float* Vs = Kt + 64*68;      // 64*64
    float* Ps = Vs + 4096;       // 64*68
    int qt = blockIdx.x, h = blockIdx.y, b = blockIdx.z;
    int tid = threadIdx.x;
    int tx = tid & 15, ty = tid >> 4;
    int q0 = ty*4, k0 = tx*4;

    const float* Qbase = g_q + (((size_t)b*NH + h)*S_ + (size_t)qt*64)*HD;
    #pragma unroll
    for (int it = 0; it < 4; it++) {
        int lin = tid + it*256;
        int r = lin >> 4, c = (lin & 15)*4;
        float4 v = *reinterpret_cast<const float4*>(&Qbase[(size_t)r*HD + c]);
        Qs[r*64+c+0] = v.x*0.125f; Qs[r*64+c+1] = v.y*0.125f;
        Qs[r*64+c+2] = v.z*0.125f; Qs[r*64+c+3] = v.w*0.125f;
    }

    float O[4][4];
    float mrun[4], lrun[4];
    #pragma unroll
    for (int i = 0; i < 4; i++) {
        mrun[i] = -1e30f; lrun[i] = 0.f;
        #pragma unroll
        for (int j = 0; j < 4; j++) O[i][j] = 0.f;
    }

    int kvh = h >> 2;
    const float* Kbase = g_k + ((size_t)b*NKV + kvh)*S_*HD;
    const float* Vbase = g_v + ((size_t)b*NKV + kvh)*S_*HD;

    for (int kt = 0; kt <= qt; kt++) {
        __syncthreads();
        {
            int r = tid >> 2, q = tid & 3;
            const float* krow = &Kbase[(size_t)(kt*64 + r)*HD + q*16];
            #pragma unroll
            for (int c4 = 0; c4 < 4; c4++) {
                float4 v = *reinterpret_cast<const float4*>(&krow[c4*4]);
                int d = q*16 + c4*4;
                Kt[(d+0)*68 + r] = v.x; Kt[(d+1)*68 + r] = v.y;
                Kt[(d+2)*68 + r] = v.z; Kt[(d+3)*68 + r] = v.w;
            }
        }
        #pragma unroll
        for (int it = 0; it < 4; it++) {
            int lin = tid + it*256;
            int r = lin >> 4, c = (lin & 15)*4;
            *reinterpret_cast<float4*>(&Vs[r*64+c]) =
                *reinterpret_cast<const float4*>(&Vbase[(size_t)(kt*64 + r)*HD + c]);
        }
        __syncthreads();

        float acc[4][4];
        #pragma unroll
        for (int i = 0; i < 4; i++)
            #pragma unroll
            for (int j = 0; j < 4; j++) acc[i][j] = 0.f;
        #pragma unroll 8
        for (int d = 0; d < 64; d++) {
            float a[4];
            #pragma unroll
            for (int i = 0; i < 4; i++) a[i] = Qs[(q0+i)*64 + d];
            float4 bv = *reinterpret_cast<const float4*>(&Kt[d*68 + k0]);
            #pragma unroll
            for (int i = 0; i < 4; i++) {
                acc[i][0] += a[i]*bv.x; acc[i][1] += a[i]*bv.y;
                acc[i][2] += a[i]*bv.z; acc[i][3] += a[i]*bv.w;
            }
        }
        if (kt == qt) {
            #pragma unroll
            for (int i = 0; i < 4; i++)
                #pragma unroll
                for (int j = 0; j < 4; j++)
                    if (k0 + j > q0 + i) acc[i][j] = -1e30f;
        }
        #pragma unroll
        for (int i = 0; i < 4; i++) {
            float rmax = fmaxf(fmaxf(acc[i][0], acc[i][1]), fmaxf(acc[i][2], acc[i][3]));
            #pragma unroll
            for (int off = 1; off < 16; off <<= 1)
                rmax = fmaxf(rmax, __shfl_xor_sync(0xffffffffu, rmax, off));
            float tmax = fmaxf(mrun[i], rmax);
            float corr = __expf(mrun[i] - tmax);
            mrun[i] = tmax;
            float p0 = __expf(acc[i][0] - tmax), p1 = __expf(acc[i][1] - tmax);
            float p2 = __expf(acc[i][2] - tmax), p3 = __expf(acc[i][3] - tmax);
            float rsum = p0 + p1 + p2 + p3;
            #pragma unroll
            for (int off = 1; off < 16; off <<= 1)
                rsum += __shfl_xor_sync(0xffffffffu, rsum, off);
            lrun[i] = lrun[i]*corr + rsum;
            #pragma unroll
            for (int j = 0; j < 4; j++) O[i][j] *= corr;
            Ps[(q0+i)*68 + k0+0] = p0; Ps[(q0+i)*68 + k0+1] = p1;
            Ps[(q0+i)*68 + k0+2] = p2; Ps[(q0+i)*68 + k0+3] = p3;
        }
        __syncthreads();
        #pragma unroll 8
        for (int kk = 0; kk < 64; kk++) {
            float a[4];
            #pragma unroll
            for (int i = 0; i < 4; i++) a[i] = Ps[(q0+i)*68 + kk];
            float4 bv = *reinterpret_cast<const float4*>(&Vs[kk*64 + k0]);
            #pragma unroll
            for (int i = 0; i < 4; i++) {
                O[i][0] += a[i]*bv.x; O[i][1] += a[i]*bv.y;
                O[i][2] += a[i]*bv.z; O[i][3] += a[i]*bv.w;
            }
        }
    }
    #pragma unroll
    for (int i = 0; i < 4; i++) {
        float inv = 1.f / lrun[i];
        float4 v = make_float4(O[i][0]*inv, O[i][1]*inv, O[i][2]*inv, O[i][3]*inv);
        *reinterpret_cast<float4*>(
            &g_ao[((size_t)(b*S_ + qt*64 + q0 + i))*DM + h*HD + k0]) = v;
    }
}

// ---------------- host launch with size-based input routing ----------------
extern "C" void kernel_launch(void* const* d_in, const int* in_sizes, int n_in,
                              void* d_out, int out_size) {
    (void)out_size;
    const float *x = 0, *Wq = 0, *Wk = 0, *Wv = 0, *Wo = 0, *M0 = 0;
    const float *ew = 0, *eb = 0, *aw = 0, *ab = 0, *gw = 0, *gb = 0;
    int n1M = 0, n256K = 0, n2K = 0, nB = 0;
    for (int i = 0; i < n_in; i++) {
        const float* p = (const float*)d_in[i];
        switch (in_sizes[i]) {
            case 8388608: x = p; break;
            case  524288: M0 = p; break;
            case 1048576: if (n1M++ == 0) Wq = p; else Wo = p; break;
            case  262144: if (n256K++ == 0) Wk = p; else Wv = p; break;
            case    2048: { if (n2K == 0) ew = p; else if (n2K == 1) aw = p; else gw = p; n2K++; } break;
            case       2: { if (nB == 0) eb = p; else if (nB == 1) ab = p; else gb = p; nB++; } break;
            default: break;
        }
    }
    float* out = (float*)d_out;

    float *pWcat = 0, *pQkv = 0, *pAo = 0;
    cudaGetSymbolAddress((void**)&pWcat, g_Wcat);
    cudaGetSymbolAddress((void**)&pQkv,  g_qkv);
    cudaGetSymbolAddress((void**)&pAo,   g_ao);

    cudaFuncSetAttribute(k_attn, cudaFuncAttributeMaxDynamicSharedMemorySize, 70000);

    k_trig<<<(S_*32 + 255)/256, 256>>>();
    k_prep<<<(int)(((size_t)DM*NCOLS + 255)/256), 256>>>(Wq, Wk, Wv, M0);

    // fused projection GEMM (bf16 tensor cores): qkv = x @ Wcat
    k_mma<<<dim3(NCOLS/128, TOK/128), 256>>>(x, pWcat, pQkv, TOK, NCOLS, DM);

    // low-rank memory machinery
    k_chunkstats<<<B_*NC, 512>>>(x, ew, eb, aw, ab);
    k_m0norm<<<2, 256>>>(M0);
    k_m0proj<<<B_*NC, 256>>>();
    k_recur<<<dim3(B_, 2), 256>>>(gw, gb);
    k_dtok<<<dim3(S_/32, B_), 256>>>(x);
    k_epilogue<<<B_*S_, 256>>>();

    // attention + output projection
    k_attn<<<dim3(S_/64, NH, B_), 256, 70000>>>();
    k_mma<<<dim3(DM/128, TOK/128), 256>>>(pAo, Wo, out, TOK, DM, DM);
}

// round 15
// speedup vs baseline: 138.7049x; 1.2628x over previous
#include <cuda_runtime.h>
#include <cuda_bf16.h>
#include <math.h>
#include <stdint.h>

#define B_  4
#define S_  2048
#define DM  1024
#define NH  16
#define NKV 4
#define HD  64
#define KVD 256
#define CH  64
#define NC  32
#define TOK (B_*S_)
#define NCOLS 2048

// ---------------- device scratch ----------------
__device__ float g_qkv[(size_t)TOK*NCOLS];
__device__ __nv_bfloat16 g_xhi[(size_t)TOK*DM];
__device__ __nv_bfloat16 g_xlo[(size_t)TOK*DM];
__device__ __nv_bfloat16 g_wthi[(size_t)NCOLS*DM];
__device__ __nv_bfloat16 g_wtlo[(size_t)NCOLS*DM];
__device__ __nv_bfloat16 g_wothi[(size_t)DM*DM];
__device__ __nv_bfloat16 g_wotlo[(size_t)DM*DM];
__device__ __nv_bfloat16 g_aohi[(size_t)TOK*DM];
__device__ __nv_bfloat16 g_aolo[(size_t)TOK*DM];
__device__ float g_cmean[B_*NC*DM];
__device__ float g_kmean[B_*NC*DM];
__device__ float g_inorm[TOK];
__device__ float g_eta[B_*2*NC];
__device__ float g_alpha[B_*2*NC];
__device__ float g_mk0[B_*2*NC*KVD];
__device__ float g_mv0[B_*2*NC*KVD];
__device__ float g_m0n2[2];
__device__ float g_U[B_*2*NC*KVD];
__device__ float g_Qret[B_*2*NC];
__device__ float g_Wret[B_*2*NC*NC];
__device__ float g_D[(size_t)TOK*NC];
__device__ float g_q[(size_t)B_*NH*S_*HD];
__device__ float g_k[(size_t)B_*NKV*S_*HD];
__device__ float g_v[(size_t)B_*NKV*S_*HD];
__device__ float g_cos[S_*32];
__device__ float g_sin[S_*32];

#define LOG_ROPE_BASE 13.122363377404331

__device__ __forceinline__ uint32_t smem_to_u32(const void* p) {
    uint32_t a;
    asm("{ .reg .u64 t; cvta.to.shared.u64 t, %1; cvt.u32.u64 %0, t; }" : "=r"(a) : "l"(p));
    return a;
}
__device__ __forceinline__ void cp16(uint32_t dst, const void* src) {
    asm volatile("cp.async.cg.shared.global [%0], [%1], 16;" :: "r"(dst), "l"(src) : "memory");
}
__device__ __forceinline__ void cp_commit() {
    asm volatile("cp.async.commit_group;" ::: "memory");
}
template<int N> __device__ __forceinline__ void cp_wait() {
    asm volatile("cp.async.wait_group %0;" :: "n"(N) : "memory");
}
__device__ __forceinline__ void mma_bf16(float c[4], uint32_t a0, uint32_t a1,
                                         uint32_t a2, uint32_t a3,
                                         uint32_t b0, uint32_t b1) {
    asm volatile(
        "mma.sync.aligned.m16n8k16.row.col.f32.bf16.bf16.f32 "
        "{%0,%1,%2,%3}, {%4,%5,%6,%7}, {%8,%9}, {%0,%1,%2,%3};"
        : "+f"(c[0]), "+f"(c[1]), "+f"(c[2]), "+f"(c[3])
        : "r"(a0), "r"(a1), "r"(a2), "r"(a3), "r"(b0), "r"(b1));
}
__device__ __forceinline__ float bf16_hi(float x) {
    return __bfloat162float(__float2bfloat16_rn(x));
}

// ---------------- RoPE trig table ----------------
__global__ void k_trig() {
    int idx = blockIdx.x*256 + threadIdx.x;
    if (idx >= S_*32) return;
    int pos = idx >> 5, fi = idx & 31;
    double f = exp(-(double)fi * (LOG_ROPE_BASE/32.0));
    double ds, dc;
    sincos((double)pos * f, &ds, &dc);
    g_cos[idx] = (float)dc;
    g_sin[idx] = (float)ds;
}

// ---------------- Wcat^T as bf16 hi/lo: wt[n][k] ----------------
__global__ __launch_bounds__(256) void k_prep(const float* __restrict__ Wq,
                                              const float* __restrict__ Wk,
                                              const float* __restrict__ Wv,
                                              const float* __restrict__ M0) {
    size_t idx = (size_t)blockIdx.x*256 + threadIdx.x;
    if (idx >= (size_t)NCOLS*DM) return;
    int n = (int)(idx / DM), k = (int)(idx % DM);
    float v;
    if (n < 1024)       v = Wq[(size_t)k*1024 + n];
    else if (n < 1280)  v = Wk[(size_t)k*256 + (n-1024)];
    else if (n < 1536)  v = Wv[(size_t)k*256 + (n-1280)];
    else if (n < 1792)  v = M0[(size_t)(n-1536)*DM + k];
    else                v = M0[(size_t)(KVD + (n-1792))*DM + k];
    float h = bf16_hi(v);
    g_wthi[idx] = __float2bfloat16_rn(h);
    g_wtlo[idx] = __float2bfloat16_rn(v - h);
}

// ---------------- Wo^T bf16 hi/lo ----------------
__global__ __launch_bounds__(256) void k_prepwo(const float* __restrict__ Wo) {
    size_t idx = (size_t)blockIdx.x*256 + threadIdx.x;
    if (idx >= (size_t)DM*DM) return;
    int n = (int)(idx / DM), k = (int)(idx % DM);
    float v = Wo[(size_t)k*DM + n];
    float h = bf16_hi(v);
    g_wothi[idx] = __float2bfloat16_rn(h);
    g_wotlo[idx] = __float2bfloat16_rn(v - h);
}

// ---------------- x -> bf16 hi/lo ----------------
__global__ __launch_bounds__(256) void k_convx(const float* __restrict__ x) {
    size_t i4 = (size_t)blockIdx.x*256 + threadIdx.x;
    if (i4 >= (size_t)TOK*DM/4) return;
    float4 v = reinterpret_cast<const float4*>(x)[i4];
    float h0 = bf16_hi(v.x), h1 = bf16_hi(v.y), h2 = bf16_hi(v.z), h3 = bf16_hi(v.w);
    __nv_bfloat162* hp = reinterpret_cast<__nv_bfloat162*>(g_xhi) + i4*2;
    __nv_bfloat162* lp = reinterpret_cast<__nv_bfloat162*>(g_xlo) + i4*2;
    hp[0] = __nv_bfloat162{__float2bfloat16_rn(h0), __float2bfloat16_rn(h1)};
    hp[1] = __nv_bfloat162{__float2bfloat16_rn(h2), __float2bfloat16_rn(h3)};
    lp[0] = __nv_bfloat162{__float2bfloat16_rn(v.x-h0), __float2bfloat16_rn(v.y-h1)};
    lp[1] = __nv_bfloat162{__float2bfloat16_rn(v.z-h2), __float2bfloat16_rn(v.w-h3)};
}

// ---------------- 3x bf16 GEMM, cp.async double-buffered --------------------
// C[M,N] = A[M,K] @ B^T[N,K]^T ; A,B given as bf16 hi/lo; B row n holds K elems.
// 128x128 block tile, kstep 32, 8 warps (2x4), warp 64x32.
#define TP 20               // uint32 words per smem row (16 k-pairs + 4 pad)
#define TW (128*TP)         // uint32 per tensor tile (2560)
__global__ __launch_bounds__(256) void k_mma2(
    const __nv_bfloat16* __restrict__ Ahi, const __nv_bfloat16* __restrict__ Alo,
    const __nv_bfloat16* __restrict__ Bhi, const __nv_bfloat16* __restrict__ Blo,
    float* __restrict__ C, int M, int N, int K)
{
    extern __shared__ uint32_t sm2[];
    uint32_t sbase = smem_to_u32(sm2);
    int tid = threadIdx.x, wid = tid >> 5, lane = tid & 31;
    int wm = wid >> 2, wn = wid & 3;
    int g = lane >> 2, tg = lane & 3;
    int bm = blockIdx.y * 128, bn = blockIdx.x * 128;

    float c[4][4][4];
    #pragma unroll
    for (int mt = 0; mt < 4; mt++)
        #pragma unroll
        for (int nt = 0; nt < 4; nt++)
            #pragma unroll
            for (int r = 0; r < 4; r++) c[mt][nt][r] = 0.f;

    auto stage = [&](int buf, int k0) {
        #pragma unroll
        for (int i = 0; i < 8; i++) {
            const int t = i >> 1;
            int r = (i & 1)*64 + (tid >> 2);
            int cc = tid & 3;
            const __nv_bfloat16* bp = (t == 0) ? Ahi : (t == 1) ? Alo : (t == 2) ? Bhi : Blo;
            int grow = ((t < 2) ? bm : bn) + r;
            cp16(sbase + (uint32_t)(buf*4*TW + t*TW)*4 + r*80 + cc*16,
                 bp + (size_t)grow*K + k0 + cc*8);
        }
        cp_commit();
    };

    int nst = K / 32;
    stage(0, 0);
    for (int i = 0; i < nst; i++) {
        if (i + 1 < nst) { stage((i+1) & 1, (i+1)*32); cp_wait<1>(); }
        else cp_wait<0>();
        __syncthreads();
        const uint32_t* Ah = sm2 + (i & 1)*4*TW;
        const uint32_t* Al = Ah + TW;
        const uint32_t* Bh = Al + TW;
        const uint32_t* Bl = Bh + TW;
        #pragma unroll
        for (int s = 0; s < 2; s++) {
            int p0 = s*8;
            uint32_t aHi[4][4], aLo[4][4], bHi[4][2], bLo[4][2];
            #pragma unroll
            for (int mt = 0; mt < 4; mt++) {
                int r0 = wm*64 + mt*16 + g;
                aHi[mt][0] = Ah[r0*TP + p0+tg];
                aHi[mt][1] = Ah[(r0+8)*TP + p0+tg];
                aHi[mt][2] = Ah[r0*TP + p0+tg+4];
                aHi[mt][3] = Ah[(r0+8)*TP + p0+tg+4];
                aLo[mt][0] = Al[r0*TP + p0+tg];
                aLo[mt][1] = Al[(r0+8)*TP + p0+tg];
                aLo[mt][2] = Al[r0*TP + p0+tg+4];
                aLo[mt][3] = Al[(r0+8)*TP + p0+tg+4];
            }
            #pragma unroll
            for (int nt = 0; nt < 4; nt++) {
                int col = wn*32 + nt*8 + g;
                bHi[nt][0] = Bh[col*TP + p0+tg];
                bHi[nt][1] = Bh[col*TP + p0+tg+4];
                bLo[nt][0] = Bl[col*TP + p0+tg];
                bLo[nt][1] = Bl[col*TP + p0+tg+4];
            }
            #pragma unroll
            for (int mt = 0; mt < 4; mt++)
                #pragma unroll
                for (int nt = 0; nt < 4; nt++) {
                    mma_bf16(c[mt][nt], aHi[mt][0], aHi[mt][1], aHi[mt][2], aHi[mt][3],
                             bHi[nt][0], bHi[nt][1]);
                    mma_bf16(c[mt][nt], aHi[mt][0], aHi[mt][1], aHi[mt][2], aHi[mt][3],
                             bLo[nt][0], bLo[nt][1]);
                    mma_bf16(c[mt][nt], aLo[mt][0], aLo[mt][1], aLo[mt][2], aLo[mt][3],
                             bHi[nt][0], bHi[nt][1]);
                }
        }
        __syncthreads();
    }

    #pragma unroll
    for (int mt = 0; mt < 4; mt++) {
        int row = bm + wm*64 + mt*16 + g;
        #pragma unroll
        for (int nt = 0; nt < 4; nt++) {
            int col = bn + wn*32 + nt*8 + tg*2;
            *reinterpret_cast<float2*>(&C[(size_t)row*N + col]) =
                make_float2(c[mt][nt][0], c[mt][nt][1]);
            *reinterpret_cast<float2*>(&C[(size_t)(row+8)*N + col]) =
                make_float2(c[mt][nt][2], c[mt][nt][3]);
        }
    }
}

// ---------------- per-chunk stats ----------------
__global__ __launch_bounds__(512) void k_chunkstats(const float* __restrict__ x,
                                                    const float* __restrict__ ew,
                                                    const float* __restrict__ eb,
                                                    const float* __restrict__ aw,
                                                    const float* __restrict__ ab) {
    int b = blockIdx.x >> 5, i = blockIdx.x & 31;
    const float* cx = x + ((size_t)(b*S_) + i*CH) * DM;
    __shared__ float inorm[CH];
    __shared__ float wacc[16][4];
    int tid = threadIdx.x, w = tid >> 5, lane = tid & 31;
    float a0 = 0.f, a1 = 0.f, a2 = 0.f, a3 = 0.f;
    for (int t = w; t < CH; t += 16) {
        const float* row = cx + (size_t)t * DM;
        float sq = 0.f, d0 = 0.f, d1 = 0.f, d2 = 0.f, d3 = 0.f;
        for (int d = lane; d < DM; d += 32) {
            float v = row[d];
            sq += v*v;
            d0 += v*ew[d];    d1 += v*ew[DM+d];
            d2 += v*aw[d];    d3 += v*aw[DM+d];
        }
        #pragma unroll
        for (int off = 16; off; off >>= 1) {
            sq += __shfl_xor_sync(0xffffffffu, sq, off);
            d0 += __shfl_xor_sync(0xffffffffu, d0, off);
            d1 += __shfl_xor_sync(0xffffffffu, d1, off);
            d2 += __shfl_xor_sync(0xffffffffu, d2, off);
            d3 += __shfl_xor_sync(0xffffffffu, d3, off);
        }
        if (lane == 0) {
            float in = 1.f / fmaxf(sqrtf(sq), 1e-5f);
            inorm[t] = in;
            g_inorm[b*S_ + i*CH + t] = in;
            a0 += 1.f/(1.f + expf(-(d0 + eb[0])));
            a1 += 1.f/(1.f + expf(-(d1 + eb[1])));
            a2 += 1.f/(1.f + expf(-(d2 + ab[0])));
            a3 += 1.f/(1.f + expf(-(d3 + ab[1])));
        }
    }
    if (lane == 0) { wacc[w][0]=a0; wacc[w][1]=a1; wacc[w][2]=a2; wacc[w][3]=a3; }
    __syncthreads();
    if (tid == 0) {
        float e0=0.f,e1=0.f,l0=0.f,l1=0.f;
        for (int ww = 0; ww < 16; ww++) { e0+=wacc[ww][0]; e1+=wacc[ww][1]; l0+=wacc[ww][2]; l1+=wacc[ww][3]; }
        g_eta  [(b*2+0)*NC+i] = 0.2f * e0 * (1.f/64.f);
        g_eta  [(b*2+1)*NC+i] = 0.2f * e1 * (1.f/64.f);
        g_alpha[(b*2+0)*NC+i] = 0.5f + 0.5f * l0 * (1.f/64.f);
        g_alpha[(b*2+1)*NC+i] = 0.5f + 0.5f * l1 * (1.f/64.f);
    }
    __syncthreads();
    for (int d = tid; d < DM; d += 512) {
        float sc = 0.f, sk = 0.f;
        for (int t = 0; t < CH; t++) {
            float v = cx[(size_t)t*DM + d];
            sc += v;
            sk += v * inorm[t];
        }
        g_cmean[(b*NC+i)*DM + d] = sc * (1.f/64.f);
        g_kmean[(b*NC+i)*DM + d] = sk * (1.f/64.f);
    }
}

// ---------------- ||M0||^2 ----------------
__global__ __launch_bounds__(256) void k_m0norm(const float* __restrict__ M0) {
    int m = blockIdx.x;
    __shared__ float red[8];
    float s = 0.f;
    const float* p = M0 + (size_t)m * KVD * DM;
    for (int idx = threadIdx.x; idx < KVD*DM; idx += 256) { float v = p[idx]; s += v*v; }
    #pragma unroll
    for (int off = 16; off; off >>= 1) s += __shfl_xor_sync(0xffffffffu, s, off);
    int w = threadIdx.x >> 5, lane = threadIdx.x & 31;
    if (lane == 0) red[w] = s;
    __syncthreads();
    if (threadIdx.x == 0) {
        float t = 0.f;
        for (int ww = 0; ww < 8; ww++) t += red[ww];
        g_m0n2[m] = t;
    }
}

// ---------------- M0@cmean, M0@kmean from qkv columns ----------------
__global__ __launch_bounds__(256) void k_m0proj() {
    int b = blockIdx.x >> 5, i = blockIdx.x & 31;
    int tid = threadIdx.x;
    const float* base = g_qkv + (size_t)(b*S_ + i*CH)*NCOLS;
    const float* inr = g_inorm + b*S_ + i*CH;
    for (int p = tid; p < 512; p += 256) {
        int col = 1536 + p;
        float sc = 0.f, sk = 0.f;
        for (int t = 0; t < CH; t++) {
            float v = base[(size_t)t*NCOLS + col];
            sc += v;
            sk += v * inr[t];
        }
        int m = p >> 8, o = p & 255;
        g_mv0[((b*2+m)*NC+i)*KVD + o] = sc * (1.f/64.f);
        g_mk0[((b*2+m)*NC+i)*KVD + o] = sk * (1.f/64.f);
    }
}

// ---------------- sequential low-rank recurrence ----------------
__global__ __launch_bounds__(256) void k_recur(const float* __restrict__ gw,
                                               const float* __restrict__ gb) {
    int b = blockIdx.x, m = blockIdx.y;
    __shared__ float kks[NC*NC];
    __shared__ float kcs[NC*NC];
    __shared__ float errs[NC*KVD];
    __shared__ float gates[NC], Wcur[NC];
    __shared__ float red1[8], red2[8], bc[2];
    int tid = threadIdx.x, w = tid >> 5, lane = tid & 31;
    const float* kmb = g_kmean + (size_t)b*NC*DM;
    const float* cmb = g_cmean + (size_t)b*NC*DM;
    for (int p = w; p < 2*NC*NC; p += 8) {
        int pi = (p < NC*NC) ? p : p - NC*NC;
        int i = pi >> 5, j = pi & 31;
        const float* u  = kmb + (size_t)j*DM;
        const float* vv = (p < NC*NC) ? (kmb + (size_t)i*DM) : (cmb + (size_t)i*DM);
        float s = 0.f;
        for (int d = lane; d < DM; d += 32) s += u[d]*vv[d];
        #pragma unroll
        for (int off = 16; off; off >>= 1) s += __shfl_xor_sync(0xffffffffu, s, off);
        if (lane == 0) { if (p < NC*NC) kks[i*NC+j] = s; else kcs[i*NC+j] = s; }
    }
    for (int g = w; g < NC; g += 8) {
        const float* u = kmb + (size_t)g*DM;
        float s = 0.f;
        for (int d = lane; d < DM; d += 32) s += u[d]*gw[m*DM + d];
        #pragma unroll
        for (int off = 16; off; off >>= 1) s += __shfl_xor_sync(0xffffffffu, s, off);
        if (lane == 0) gates[g] = 1.f/(1.f + expf(-(s + gb[m])));
    }
    if (tid < NC) Wcur[tid] = 0.f;
    __syncthreads();

    float Q = 1.f, N2 = g_m0n2[m];
    int bm = b*2 + m;
    int o = tid;
    for (int i = 0; i < NC; i++) {
        float vt = Q * g_mv0[(bm*NC+i)*KVD + o];
        float mk = Q * g_mk0[(bm*NC+i)*KVD + o];
        for (int j = 0; j < i; j++) {
            float we = Wcur[j] * errs[j*KVD + o];
            vt += we * kcs[i*NC+j];
            mk += we * kks[i*NC+j];
        }
        float e = vt - mk;
        errs[i*KVD + o] = e;
        g_U[(bm*NC+i)*KVD + o] = e;
        float p1 = mk*e, p2 = e*e;
        #pragma unroll
        for (int off = 16; off; off >>= 1) {
            p1 += __shfl_xor_sync(0xffffffffu, p1, off);
            p2 += __shfl_xor_sync(0xffffffffu, p2, off);
        }
        if (lane == 0) { red1[w] = p1; red2[w] = p2; }
        __syncthreads();
        if (tid == 0) {
            float s1 = 0.f, s2 = 0.f;
            for (int ww = 0; ww < 8; ww++) { s1 += red1[ww]; s2 += red2[ww]; }
            bc[0] = s1; bc[1] = s2;
        }
        __syncthreads();
        float dot1 = bc[0], errsq = bc[1];
        float gt = gates[i];
        float eta = g_eta[bm*NC+i], al = g_alpha[bm*NC+i];
        float a  = gt*al + 1.f - gt;
        float b0 = gt*eta;
        float m2 = a*a*N2 + 2.f*a*b0*dot1 + b0*b0*errsq*kks[i*NC+i];
        float s  = fminf(30.f/(sqrtf(m2) + 1e-6f), 1.f);
        if (tid < NC) g_Wret[(bm*NC+i)*NC + tid] = (tid < i) ? Wcur[tid] : 0.f;
        if (tid == 0) g_Qret[bm*NC+i] = Q;
        __syncthreads();
        if (tid < NC) { if (tid < i) Wcur[tid] *= s*a; else if (tid == i) Wcur[tid] = s*b0; }
        Q *= s*a;
        N2 = s*s*m2;
        __syncthreads();
    }
}

// ---------------- D[b,t,j] = x_t . kmean_j ----------------
__global__ __launch_bounds__(256) void k_dtok(const float* __restrict__ x) {
    __shared__ float xs[32][128];
    __shared__ float ks[32][129];
    int b = blockIdx.y, t0 = blockIdx.x * 32;
    int tid = threadIdx.x;
    int tl = tid >> 5, j = tid & 31;
    float acc[4] = {0.f, 0.f, 0.f, 0.f};
    for (int d0 = 0; d0 < DM; d0 += 128) {
        #pragma unroll
        for (int it = 0; it < 4; it++) {
            int lin = tid + it*256;
            int r = lin >> 5, q = lin & 31;
            float4 xv = *reinterpret_cast<const float4*>(&x[((size_t)(b*S_) + t0 + r)*DM + d0 + q*4]);
            *reinterpret_cast<float4*>(&xs[r][q*4]) = xv;
            float4 kv = *reinterpret_cast<const float4*>(&g_kmean[((size_t)(b*NC) + r)*DM + d0 + q*4]);
            ks[r][q*4+0] = kv.x; ks[r][q*4+1] = kv.y; ks[r][q*4+2] = kv.z; ks[r][q*4+3] = kv.w;
        }
        __syncthreads();
        #pragma unroll
        for (int tt = 0; tt < 4; tt++) {
            int t = tl + tt*8;
            float s = 0.f;
            #pragma unroll 16
            for (int d = 0; d < 128; d++) s += xs[t][d]*ks[j][d];
            acc[tt] += s;
        }
        __syncthreads();
    }
    #pragma unroll
    for (int tt = 0; tt < 4; tt++)
        g_D[((size_t)(b*S_) + t0 + tl + tt*8)*NC + j] = acc[tt];
}

// ---------------- build q(rope), k(mem+rope), v(mem) ----------------
__global__ __launch_bounds__(256) void k_epilogue() {
    int blk = blockIdx.x;
    int b = blk >> 11, pos = blk & 2047;
    int i = pos >> 6;
    int tid = threadIdx.x;
    __shared__ float wd0[NC], wd1[NC], kbuf[KVD];
    if (tid < 32) {
        float Dv = g_D[((size_t)(b*S_) + pos)*NC + tid];
        wd0[tid] = g_Wret[((b*2+0)*NC+i)*NC + tid] * Dv;
        wd1[tid] = g_Wret[((b*2+1)*NC+i)*NC + tid] * Dv;
    }
    __syncthreads();
    const float* row = g_qkv + (size_t)(b*S_ + pos) * NCOLS;
    float q0 = g_Qret[(b*2+0)*NC+i], q1 = g_Qret[(b*2+1)*NC+i];
    int o = tid;
    float kval = row[1024 + o] + q0 * row[1536 + o];
    float vval = row[1280 + o] + q1 * row[1792 + o];
    const float* U0 = g_U + (size_t)(b*2+0)*NC*KVD;
    const float* U1 = g_U + (size_t)(b*2+1)*NC*KVD;
    #pragma unroll 8
    for (int j = 0; j < NC; j++) {
        kval += wd0[j] * U0[j*KVD + o];
        vval += wd1[j] * U1[j*KVD + o];
    }
    kbuf[o] = kval;
    __syncthreads();
    int d = o & 63, kv = o >> 6;
    float cs = g_cos[pos*32 + (d & 31)], sn = g_sin[pos*32 + (d & 31)];
    float rot = (d < 32) ? -kbuf[kv*64 + d + 32] : kbuf[kv*64 + d - 32];
    size_t kidx = (((size_t)(b*NKV) + kv)*S_ + pos)*HD + d;
    g_k[kidx] = kval*cs + rot*sn;
    g_v[kidx] = vval;
    for (int oq = tid; oq < DM; oq += 256) {
        float qv = row[oq];
        int dd = oq & 63, h = oq >> 6;
        float part = row[h*64 + ((dd < 32) ? dd + 32 : dd - 32)];
        float rq = (dd < 32) ? -part : part;
        float c2 = g_cos[pos*32 + (dd & 31)], s2 = g_sin[pos*32 + (dd & 31)];
        g_q[(((size_t)(b*NH) + h)*S_ + pos)*HD + dd] = qv*c2 + rq*s2;
    }
}

// ---------------- causal flash attention (SIMT 4x4), bf16 hi/lo output ------
__global__ __launch_bounds__(256) void k_attn() {
    extern __shared__ float sm[];
    float* Qs = sm;
    float* Kt = Qs + 4096;
    float* Vs = Kt + 64*68;
    float* Ps = Vs + 4096;
    int qt = blockIdx.x, h = blockIdx.y, b = blockIdx.z;
    int tid = threadIdx.x;
    int tx = tid & 15, ty = tid >> 4;
    int q0 = ty*4, k0 = tx*4;

    const float* Qbase = g_q + (((size_t)b*NH + h)*S_ + (size_t)qt*64)*HD;
    #pragma unroll
    for (int it = 0; it < 4; it++) {
        int lin = tid + it*256;
        int r = lin >> 4, c = (lin & 15)*4;
        float4 v = *reinterpret_cast<const float4*>(&Qbase[(size_t)r*HD + c]);
        Qs[r*64+c+0] = v.x*0.125f; Qs[r*64+c+1] = v.y*0.125f;
        Qs[r*64+c+2] = v.z*0.125f; Qs[r*64+c+3] = v.w*0.125f;
    }

    float O[4][4];
    float mrun[4], lrun[4];
    #pragma unroll
    for (int i = 0; i < 4; i++) {
        mrun[i] = -1e30f; lrun[i] = 0.f;
        #pragma unroll
        for (int j = 0; j < 4; j++) O[i][j] = 0.f;
    }

    int kvh = h >> 2;
    const float* Kbase = g_k + ((size_t)b*NKV + kvh)*S_*HD;
    const float* Vbase = g_v + ((size_t)b*NKV + kvh)*S_*HD;

    for (int kt = 0; kt <= qt; kt++) {
        __syncthreads();
        {
            int r = tid >> 2, q = tid & 3;
            const float* krow = &Kbase[(size_t)(kt*64 + r)*HD + q*16];
            #pragma unroll
            for (int c4 = 0; c4 < 4; c4++) {
                float4 v = *reinterpret_cast<const float4*>(&krow[c4*4]);
                int d = q*16 + c4*4;
                Kt[(d+0)*68 + r] = v.x; Kt[(d+1)*68 + r] = v.y;
                Kt[(d+2)*68 + r] = v.z; Kt[(d+3)*68 + r] = v.w;
            }
        }
        #pragma unroll
        for (int it = 0; it < 4; it++) {
            int lin = tid + it*256;
            int r = lin >> 4, c = (lin & 15)*4;
            *reinterpret_cast<float4*>(&Vs[r*64+c]) =
                *reinterpret_cast<const float4*>(&Vbase[(size_t)(kt*64 + r)*HD + c]);
        }
        __syncthreads();

        float acc[4][4];
        #pragma unroll
        for (int i = 0; i < 4; i++)
            #pragma unroll
            for (int j = 0; j < 4; j++) acc[i][j] = 0.f;
        #pragma unroll 8
        for (int d = 0; d < 64; d++) {
            float a[4];
            #pragma unroll
            for (int i = 0; i < 4; i++) a[i] = Qs[(q0+i)*64 + d];
            float4 bv = *reinterpret_cast<const float4*>(&Kt[d*68 + k0]);
            #pragma unroll
            for (int i = 0; i < 4; i++) {
                acc[i][0] += a[i]*bv.x; acc[i][1] += a[i]*bv.y;
                acc[i][2] += a[i]*bv.z; acc[i][3] += a[i]*bv.w;
            }
        }
        if (kt == qt) {
            #pragma unroll
            for (int i = 0; i < 4; i++)
                #pragma unroll
                for (int j = 0; j < 4; j++)
                    if (k0 + j > q0 + i) acc[i][j] = -1e30f;
        }
        #pragma unroll
        for (int i = 0; i < 4; i++) {
            float rmax = fmaxf(fmaxf(acc[i][0], acc[i][1]), fmaxf(acc[i][2], acc[i][3]));
            #pragma unroll
            for (int off = 1; off < 16; off <<= 1)
                rmax = fmaxf(rmax, __shfl_xor_sync(0xffffffffu, rmax, off));
            float tmax = fmaxf(mrun[i], rmax);
            float corr = __expf(mrun[i] - tmax);
            mrun[i] = tmax;
            float p0 = __expf(acc[i][0] - tmax), p1 = __expf(acc[i][1] - tmax);
            float p2 = __expf(acc[i][2] - tmax), p3 = __expf(acc[i][3] - tmax);
            float rsum = p0 + p1 + p2 + p3;
            #pragma unroll
            for (int off = 1; off < 16; off <<= 1)
                rsum += __shfl_xor_sync(0xffffffffu, rsum, off);
            lrun[i] = lrun[i]*corr + rsum;
            #pragma unroll
            for (int j = 0; j < 4; j++) O[i][j] *= corr;
            Ps[(q0+i)*68 + k0+0] = p0; Ps[(q0+i)*68 + k0+1] = p1;
            Ps[(q0+i)*68 + k0+2] = p2; Ps[(q0+i)*68 + k0+3] = p3;
        }
        __syncthreads();
        #pragma unroll 8
        for (int kk = 0; kk < 64; kk++) {
            float a[4];
            #pragma unroll
            for (int i = 0; i < 4; i++) a[i] = Ps[(q0+i)*68 + kk];
            float4 bv = *reinterpret_cast<const float4*>(&Vs[kk*64 + k0]);
            #pragma unroll
            for (int i = 0; i < 4; i++) {
                O[i][0] += a[i]*bv.x; O[i][1] += a[i]*bv.y;
                O[i][2] += a[i]*bv.z; O[i][3] += a[i]*bv.w;
            }
        }
    }
    #pragma unroll
    for (int i = 0; i < 4; i++) {
        float inv = 1.f / lrun[i];
        size_t off = ((size_t)(b*S_ + qt*64 + q0 + i))*DM + h*HD + k0;
        #pragma unroll
        for (int j = 0; j < 4; j++) {
            float v = O[i][j]*inv;
            float hh = bf16_hi(v);
            g_aohi[off + j] = __float2bfloat16_rn(hh);
            g_aolo[off + j] = __float2bfloat16_rn(v - hh);
        }
    }
}

// ---------------- host launch with size-based input routing ----------------
extern "C" void kernel_launch(void* const* d_in, const int* in_sizes, int n_in,
                              void* d_out, int out_size) {
    (void)out_size;
    const float *x = 0, *Wq = 0, *Wk = 0, *Wv = 0, *Wo = 0, *M0 = 0;
    const float *ew = 0, *eb = 0, *aw = 0, *ab = 0, *gw = 0, *gb = 0;
    int n1M = 0, n256K = 0, n2K = 0, nB = 0;
    for (int i = 0; i < n_in; i++) {
        const float* p = (const float*)d_in[i];
        switch (in_sizes[i]) {
            case 8388608: x = p; break;
            case  524288: M0 = p; break;
            case 1048576: if (n1M++ == 0) Wq = p; else Wo = p; break;
            case  262144: if (n256K++ == 0) Wk = p; else Wv = p; break;
            case    2048: { if (n2K == 0) ew = p; else if (n2K == 1) aw = p; else gw = p; n2K++; } break;
            case       2: { if (nB == 0) eb = p; else if (nB == 1) ab = p; else gb = p; nB++; } break;
            default: break;
        }
    }
    float* out = (float*)d_out;

    float* pQkv = 0;
    cudaGetSymbolAddress((void**)&pQkv, g_qkv);
    __nv_bfloat16 *pXhi = 0, *pXlo = 0, *pWthi = 0, *pWtlo = 0;
    __nv_bfloat16 *pWohi = 0, *pWolo = 0, *pAohi = 0, *pAolo = 0;
    cudaGetSymbolAddress((void**)&pXhi, g_xhi);
    cudaGetSymbolAddress((void**)&pXlo, g_xlo);
    cudaGetSymbolAddress((void**)&pWthi, g_wthi);
    cudaGetSymbolAddress((void**)&pWtlo, g_wtlo);
    cudaGetSymbolAddress((void**)&pWohi, g_wothi);
    cudaGetSymbolAddress((void**)&pWolo, g_wotlo);
    cudaGetSymbolAddress((void**)&pAohi, g_aohi);
    cudaGetSymbolAddress((void**)&pAolo, g_aolo);

    cudaFuncSetAttribute(k_attn, cudaFuncAttributeMaxDynamicSharedMemorySize, 70000);
    cudaFuncSetAttribute(k_mma2, cudaFuncAttributeMaxDynamicSharedMemorySize, 82000);

    // ordered so GEMM1 is the 6th launch (ncu -s 5 -c 1 captures it)
    k_trig<<<(S_*32 + 255)/256, 256>>>();
    k_prep<<<(int)(((size_t)NCOLS*DM + 255)/256), 256>>>(Wq, Wk, Wv, M0);
    k_prepwo<<<(int)(((size_t)DM*DM + 255)/256), 256>>>(Wo);
    k_convx<<<(int)(((size_t)TOK*DM/4 + 255)/256), 256>>>(x);
    k_chunkstats<<<B_*NC, 512>>>(x, ew, eb, aw, ab);
    k_mma2<<<dim3(NCOLS/128, TOK/128), 256, 82000>>>(pXhi, pXlo, pWthi, pWtlo,
                                                     pQkv, TOK, NCOLS, DM);
    k_m0norm<<<2, 256>>>(M0);
    k_dtok<<<dim3(S_/32, B_), 256>>>(x);
    k_m0proj<<<B_*NC, 256>>>();
    k_recur<<<dim3(B_, 2), 256>>>(gw, gb);
    k_epilogue<<<B_*S_, 256>>>();
    k_attn<<<dim3(S_/64, NH, B_), 256, 70000>>>();
    k_mma2<<<dim3(DM/128, TOK/128), 256, 82000>>>(pAohi, pAolo, pWohi, pWolo,
                                                  out, TOK, DM, DM);
}